// round 11
// baseline (speedup 1.0000x reference)
#include <cuda_runtime.h>
#include <cuda_fp16.h>

// SConv R10: R9 with warp tile 64x64 (2Mx2N, 128-thr CTA) to cut fragment
// duplication (B LDSM x4 -> x2). 2 CTAs/SM, K=64 stages, cp.async 3-stage ring.

#define B_  16
#define C1  128
#define C2  256
#define H_  128
#define W_  128
#define HW  (H_*W_)
#define EPSBN 1e-5f

typedef unsigned int uint;

#define XVSZ ((size_t)B_ * C1 * HW)

__device__ __half g_xv [3 * XVSZ];                // x fp16, col-shift variants -1/0/+1
__device__ __half g_yi [(size_t)B_ * C2 * HW];    // y fp16 plain (identity)
__device__ __half g_ysh[(size_t)B_ * C2 * HW];    // y fp16 pre-shifted per group
__device__ __half g_wA16[36 * 2 * 4096];          // conv w, frag order
__device__ __half g_wB16[ 8 * 2 * 4096];          // 1x1 w, frag order

__device__ __forceinline__ float silu_f(float v) { return v / (1.0f + __expf(-v)); }
__device__ __forceinline__ uint smem_u32(const void* p) {
    uint a;
    asm("{ .reg .u64 t; cvta.to.shared.u64 t, %1; cvt.u32.u64 %0, t; }" : "=r"(a) : "l"(p));
    return a;
}

#define MMA16(d, a, b0v, b1v) \
    asm volatile("mma.sync.aligned.m16n8k16.row.col.f32.f16.f16.f32 " \
        "{%0,%1,%2,%3}, {%4,%5,%6,%7}, {%8,%9}, {%0,%1,%2,%3};" \
        : "+f"((d)[0]), "+f"((d)[1]), "+f"((d)[2]), "+f"((d)[3]) \
        : "r"((a).x), "r"((a).y), "r"((a).z), "r"((a).w), "r"(b0v), "r"(b1v))

#define CP_A16(sm, gp) \
    asm volatile("cp.async.cg.shared.global [%0], [%1], 16;" :: "r"(sm), "l"(gp))
#define CP_A16Z(sm, gp, sz) \
    asm volatile("cp.async.cg.shared.global [%0], [%1], 16, %2;" :: "r"(sm), "l"(gp), "r"(sz))
#define CP_COMMIT() asm volatile("cp.async.commit_group;")
#define CP_WAIT1()  asm volatile("cp.async.wait_group 1;" ::: "memory")
#define CP_WAIT0()  asm volatile("cp.async.wait_group 0;" ::: "memory")

// Sub-chunk (K=32): A 8192 B (frag order) + B 8192 B (row-major [kk 32][n 128],
// 256B rows, 16B-granule XOR swizzle). Stage = 2 sub-chunks = 32 KB.
#define A_BYTES 8192
#define B_BYTES 8192
#define CHUNK   (A_BYTES + B_BYTES)   // 16384
#define STAGE   (2 * CHUNK)           // 32768
#define NSTG    3
#define DSMEM_BYTES (NSTG * STAGE)    // 98304 per CTA, 2 CTAs/SM

#define NTHR 128

// --------------------------------------------------------- repack kernels --
__device__ __forceinline__ int fragoff(int m, int kk) {
    return (((kk >> 4) * 8 + (m >> 4)) * 32 + (((m & 7) << 2) | ((kk >> 1) & 3))) * 8
         + (((kk >> 3) & 1) * 2 + ((m >> 3) & 1)) * 2 + (kk & 1);
}
__global__ __launch_bounds__(256) void k_repack_conv(const float* __restrict__ wc) {
    int idx = blockIdx.x * 256 + threadIdx.x;
    if (idx >= C2 * C1 * 9) return;
    int tap = idx % 9, rest = idx / 9;
    int ic = rest % C1, oc = rest / C1;
    int it = (ic >> 5) * 9 + tap;
    g_wA16[(size_t)(it * 2 + (oc >> 7)) * 4096 + fragoff(oc & 127, ic & 31)] =
        __float2half_rn(wc[idx]);
}
__global__ __launch_bounds__(256) void k_repack_pw(const float* __restrict__ w1) {
    int idx = blockIdx.x * 256 + threadIdx.x;
    if (idx >= C2 * C2) return;
    int ic = idx % C2, oc = idx / C2;
    g_wB16[(size_t)((ic >> 5) * 2 + (oc >> 7)) * 4096 + fragoff(oc & 127, ic & 31)] =
        __float2half_rn(w1[idx]);
}

__global__ __launch_bounds__(256) void k_prep_x(const float* __restrict__ x) {
    size_t i = (size_t)blockIdx.x * 256 + threadIdx.x;   // over XVSZ/8
    size_t base = i * 8;
    int w0 = (int)(base & 127);
    const float* p = x + base;
    float4 a  = __ldg((const float4*)p);
    float4 b4 = __ldg((const float4*)(p + 4));
    float xm1 = (w0 > 0)   ? __ldg(p - 1) : 0.f;
    float xp8 = (w0 < 120) ? __ldg(p + 8) : 0.f;
    __half2* v0 = (__half2*)g_xv + i * 4;
    __half2* v1 = (__half2*)(g_xv + XVSZ) + i * 4;
    __half2* v2 = (__half2*)(g_xv + 2 * XVSZ) + i * 4;
    v1[0] = __floats2half2_rn(a.x, a.y);  v1[1] = __floats2half2_rn(a.z, a.w);
    v1[2] = __floats2half2_rn(b4.x, b4.y); v1[3] = __floats2half2_rn(b4.z, b4.w);
    v0[0] = __floats2half2_rn(xm1, a.x);  v0[1] = __floats2half2_rn(a.y, a.z);
    v0[2] = __floats2half2_rn(a.w, b4.x); v0[3] = __floats2half2_rn(b4.y, b4.z);
    v2[0] = __floats2half2_rn(a.y, a.z);  v2[1] = __floats2half2_rn(a.w, b4.x);
    v2[2] = __floats2half2_rn(b4.y, b4.z); v2[3] = __floats2half2_rn(b4.w, xp8);
}

__global__ __launch_bounds__(256) void k_zero_sh() {
    int idx = blockIdx.x * 256 + threadIdx.x;   // 524288
    if (idx >= 4 * 16 * 64 * 128) return;
    int grp = idx >> 17, r = idx & 131071;
    int b = r >> 13, r2 = r & 8191;
    int c = r2 >> 7, p = r2 & 127;
    int oc, h, w;
    if      (grp == 0) { oc = c;       h = p;   w = 0;   }
    else if (grp == 1) { oc = 64 + c;  h = 127; w = p;   }
    else if (grp == 2) { oc = 128 + c; h = p;   w = 127; }
    else               { oc = 192 + c; h = 0;   w = p;   }
    g_ysh[(((size_t)b * C2 + oc) << 14) + h * W_ + w] = __float2half_rn(0.f);
}

// --------------------------------------------------------- staging helpers --
// 128 threads: A sub-chunk = 8192 B = 512 x 16B -> 4 per thread.
__device__ __forceinline__ void cp_issue_A(uint Asm, const __half* src, int tid) {
    const char* g = (const char*)src;
#pragma unroll
    for (int i = 0; i < 4; ++i)
        CP_A16(Asm + i * 2048 + tid * 16, g + i * 2048 + tid * 16);
}
// B: thread owns granule column g (=tid&15), rows kk0+8i (kk0=tid>>4, i 0..3).
__device__ __forceinline__ void cp_issue_B(uint Bsm, const __half* vbase,
                                           int kk0, uint gxor, int hs, int wcol) {
    uint ok = ((uint)hs < 128u) ? 16u : 0u;
    int hsc = (hs < 0) ? 0 : (hs > 127 ? 127 : hs);
    const char* s = (const char*)(vbase + (size_t)kk0 * HW + hsc * W_ + wcol);
    uint d = Bsm + kk0 * 256 + gxor;      // (kk0+8i)&7 == kk0&7 -> same gxor
#pragma unroll
    for (int i = 0; i < 4; ++i)
        CP_A16Z(d + i * 2048, s + (size_t)i * 8 * HW * 2, ok);
}

// ----------------------------------------------------------------- MMA -----
// warp tile 64oc x 64px: wm=wrp>>1 (0..1), wn=wrp&1. mf 0..3, nf 0..7.
__device__ __forceinline__ void mma_chunk(uint Asm, uint Bsm, int wm, int wn,
                                          int lane, float acc[4][8][4]) {
    const int j = lane >> 3, r = lane & 7;
    const int jk = (j & 1) << 3, jn = j >> 1;
#pragma unroll
    for (int ks = 0; ks < 2; ++ks) {
        uint4 a[4];
#pragma unroll
        for (int mf = 0; mf < 4; ++mf) {
            uint ad = Asm + (((ks * 8 + wm * 4 + mf) * 32 + lane) << 4);
            asm volatile("ld.shared.v4.b32 {%0,%1,%2,%3}, [%4];"
                : "=r"(a[mf].x), "=r"(a[mf].y), "=r"(a[mf].z), "=r"(a[mf].w) : "r"(ad));
        }
        uint bf[8][2];
#pragma unroll
        for (int p = 0; p < 4; ++p) {
            int krow = ks * 16 + jk + r;
            int oct  = wn * 8 + 2 * p + jn;
            uint ad = Bsm + krow * 256 + ((uint)(oct ^ (krow & 7)) << 4);
            uint d0, d1, d2, d3;
            asm volatile("ldmatrix.sync.aligned.m8n8.x4.trans.shared.b16 "
                "{%0,%1,%2,%3}, [%4];"
                : "=r"(d0), "=r"(d1), "=r"(d2), "=r"(d3) : "r"(ad));
            bf[2 * p][0] = d0; bf[2 * p][1] = d1;
            bf[2 * p + 1][0] = d2; bf[2 * p + 1][1] = d3;
        }
#pragma unroll
        for (int mf = 0; mf < 4; ++mf)
#pragma unroll
            for (int nf = 0; nf < 8; ++nf)
                MMA16(acc[mf][nf], a[mf], bf[nf][0], bf[nf][1]);
    }
}

// ------------------------------------------------------ conv3x3 + BN + SiLU
__global__ __launch_bounds__(NTHR, 2) void k_conv3(
    const float* __restrict__ gamma, const float* __restrict__ beta,
    const float* __restrict__ mean,  const float* __restrict__ var)
{
    extern __shared__ __align__(16) char dsm[];
    const uint smb = smem_u32(dsm);

    const int tid = threadIdx.x;
    const int wrp = tid >> 5, lane = tid & 31;
    const int wm = wrp >> 1, wn = wrp & 1;
    const int kk0 = tid >> 4, g = tid & 15;
    const int wcol = g * 8;
    const uint gxor = ((uint)(g ^ (kk0 & 7))) << 4;
    const int h0  = blockIdx.x;
    const int ocg = blockIdx.y, oc0 = ocg * 128;
    const int b   = blockIdx.z;

    float acc[4][8][4];
#pragma unroll
    for (int i = 0; i < 4; ++i)
#pragma unroll
        for (int jj = 0; jj < 8; ++jj)
#pragma unroll
            for (int q = 0; q < 4; ++q) acc[i][jj][q] = 0.0f;

    const size_t bofs = (size_t)b * C1 * HW;
#define SUB_CONV(nit, base) do { \
        int kc_ = (nit) / 9, tap_ = (nit) - 9 * kc_; \
        int ky_ = tap_ / 3, kx_ = tap_ - 3 * ky_; \
        cp_issue_A((base), g_wA16 + (size_t)((nit) * 2 + ocg) * 4096, tid); \
        const __half* vb_ = g_xv + (size_t)kx_ * XVSZ + bofs + (size_t)kc_ * 32 * HW; \
        cp_issue_B((base) + A_BYTES, vb_, kk0, gxor, h0 + ky_ - 1, wcol); \
    } while (0)
#define ISSUE_CONV(st, s) do { \
        SUB_CONV(2 * (st),     smb + (s) * STAGE); \
        SUB_CONV(2 * (st) + 1, smb + (s) * STAGE + CHUNK); \
        CP_COMMIT(); \
    } while (0)

    ISSUE_CONV(0, 0);
    ISSUE_CONV(1, 1);

#pragma unroll 1
    for (int st = 0; st < 18; ++st) {
        if (st + 2 < 18) CP_WAIT1(); else CP_WAIT0();
        __syncthreads();
        if (st + 2 < 18) {
            int s = (st + 2) % NSTG;
            ISSUE_CONV(st + 2, s);
        }
        const uint sb = smb + (st % NSTG) * STAGE;
        mma_chunk(sb,         sb + A_BYTES,         wm, wn, lane, acc);
        mma_chunk(sb + CHUNK, sb + CHUNK + A_BYTES, wm, wn, lane, acc);
    }
#undef ISSUE_CONV
#undef SUB_CONV

    // epilogue: BN + SiLU -> g_yi (plain) + g_ysh (shifted by group)
    const int grp = ((oc0 + wm * 64) >> 6) & 3;   // warp-uniform
    const int h = h0;
#pragma unroll
    for (int mf = 0; mf < 4; ++mf) {
        const int oc_a = oc0 + wm * 64 + mf * 16 + (lane >> 2);
        const int oc_b = oc_a + 8;
        const float inva = __ldg(&gamma[oc_a]) * rsqrtf(__ldg(&var[oc_a]) + EPSBN);
        const float bba  = __ldg(&beta[oc_a]) - __ldg(&mean[oc_a]) * inva;
        const float invb = __ldg(&gamma[oc_b]) * rsqrtf(__ldg(&var[oc_b]) + EPSBN);
        const float bbb  = __ldg(&beta[oc_b]) - __ldg(&mean[oc_b]) * invb;
        const size_t ra = ((size_t)b * C2 + oc_a) * HW;
        const size_t rb = ((size_t)b * C2 + oc_b) * HW;
#pragma unroll
        for (int nf = 0; nf < 8; ++nf) {
            const int w = wn * 64 + nf * 8 + (lane & 3) * 2;
            const int off = h * W_ + w;
            float2 u, v;
            u.x = silu_f(acc[mf][nf][0] * inva + bba);
            u.y = silu_f(acc[mf][nf][1] * inva + bba);
            v.x = silu_f(acc[mf][nf][2] * invb + bbb);
            v.y = silu_f(acc[mf][nf][3] * invb + bbb);
            __half2 uh = __floats2half2_rn(u.x, u.y);
            __half2 vh = __floats2half2_rn(v.x, v.y);
            *(__half2*)(g_yi + ra + off) = uh;
            *(__half2*)(g_yi + rb + off) = vh;
            if (grp == 0) {            // dest (h, w+1)
                g_ysh[ra + off + 1] = __low2half(uh);
                g_ysh[rb + off + 1] = __low2half(vh);
                if (w < 126) {
                    g_ysh[ra + off + 2] = __high2half(uh);
                    g_ysh[rb + off + 2] = __high2half(vh);
                }
            } else if (grp == 1) {     // dest (h-1, w)
                if (h > 0) {
                    *(__half2*)(g_ysh + ra + off - W_) = uh;
                    *(__half2*)(g_ysh + rb + off - W_) = vh;
                }
            } else if (grp == 2) {     // dest (h, w-1)
                if (w > 0) {
                    g_ysh[ra + off - 1] = __low2half(uh);
                    g_ysh[rb + off - 1] = __low2half(vh);
                }
                g_ysh[ra + off] = __high2half(uh);
                g_ysh[rb + off] = __high2half(vh);
            } else {                   // dest (h+1, w)
                if (h < 127) {
                    *(__half2*)(g_ysh + ra + off + W_) = uh;
                    *(__half2*)(g_ysh + rb + off + W_) = vh;
                }
            }
        }
    }
}

// --------------------------- conv1x1(shifted y) + bias + BN + id + SiLU ----
__global__ __launch_bounds__(NTHR, 2) void k_pw(
    const float* __restrict__ b1,
    const float* __restrict__ gamma, const float* __restrict__ beta,
    const float* __restrict__ mean,  const float* __restrict__ var,
    float* __restrict__ out)
{
    extern __shared__ __align__(16) char dsm[];
    const uint smb = smem_u32(dsm);

    const int tid = threadIdx.x;
    const int wrp = tid >> 5, lane = tid & 31;
    const int wm = wrp >> 1, wn = wrp & 1;
    const int kk0 = tid >> 4, g = tid & 15;
    const int wcol = g * 8;
    const uint gxor = ((uint)(g ^ (kk0 & 7))) << 4;
    const int h0  = blockIdx.x;
    const int ocg = blockIdx.y, oc0 = ocg * 128;
    const int b   = blockIdx.z;

    float acc[4][8][4];
#pragma unroll
    for (int i = 0; i < 4; ++i)
#pragma unroll
        for (int jj = 0; jj < 8; ++jj)
#pragma unroll
            for (int q = 0; q < 4; ++q) acc[i][jj][q] = 0.0f;

    const size_t bofs = (size_t)b * C2 * HW;
#define SUB_PW(nit, base) do { \
        cp_issue_A((base), g_wB16 + (size_t)((nit) * 2 + ocg) * 4096, tid); \
        const __half* vb_ = g_ysh + bofs + (size_t)(nit) * 32 * HW; \
        cp_issue_B((base) + A_BYTES, vb_, kk0, gxor, h0, wcol); \
    } while (0)
#define ISSUE_PW(st, s) do { \
        SUB_PW(2 * (st),     smb + (s) * STAGE); \
        SUB_PW(2 * (st) + 1, smb + (s) * STAGE + CHUNK); \
        CP_COMMIT(); \
    } while (0)

    ISSUE_PW(0, 0);
    ISSUE_PW(1, 1);

#pragma unroll 1
    for (int st = 0; st < 4; ++st) {
        if (st + 2 < 4) CP_WAIT1(); else CP_WAIT0();
        __syncthreads();
        if (st + 2 < 4) {
            int s = (st + 2) % NSTG;
            ISSUE_PW(st + 2, s);
        }
        const uint sb = smb + (st % NSTG) * STAGE;
        mma_chunk(sb,         sb + A_BYTES,         wm, wn, lane, acc);
        mma_chunk(sb + CHUNK, sb + CHUNK + A_BYTES, wm, wn, lane, acc);
    }
#undef ISSUE_PW
#undef SUB_PW

    // epilogue: +bias, BN, +identity(fp16), SiLU -> out (fp32)
    const int h = h0;
#pragma unroll
    for (int mf = 0; mf < 4; ++mf) {
        const int oc_a = oc0 + wm * 64 + mf * 16 + (lane >> 2);
        const int oc_b = oc_a + 8;
        const float inva = __ldg(&gamma[oc_a]) * rsqrtf(__ldg(&var[oc_a]) + EPSBN);
        const float bba  = __ldg(&beta[oc_a]) - __ldg(&mean[oc_a]) * inva;
        const float bsa  = __ldg(&b1[oc_a]);
        const float invb = __ldg(&gamma[oc_b]) * rsqrtf(__ldg(&var[oc_b]) + EPSBN);
        const float bbb  = __ldg(&beta[oc_b]) - __ldg(&mean[oc_b]) * invb;
        const float bsb  = __ldg(&b1[oc_b]);
        const size_t ra = ((size_t)b * C2 + oc_a) * HW;
        const size_t rb = ((size_t)b * C2 + oc_b) * HW;
#pragma unroll
        for (int nf = 0; nf < 8; ++nf) {
            const int w = wn * 64 + nf * 8 + (lane & 3) * 2;
            const int off = h * W_ + w;
            float2 ida = __half22float2(*(const __half2*)(g_yi + ra + off));
            float2 idb = __half22float2(*(const __half2*)(g_yi + rb + off));
            float2 u, v; float z;
            z = (acc[mf][nf][0] + bsa) * inva + bba + ida.x; u.x = silu_f(z);
            z = (acc[mf][nf][1] + bsa) * inva + bba + ida.y; u.y = silu_f(z);
            z = (acc[mf][nf][2] + bsb) * invb + bbb + idb.x; v.x = silu_f(z);
            z = (acc[mf][nf][3] + bsb) * invb + bbb + idb.y; v.y = silu_f(z);
            *(float2*)(out + ra + off) = u;
            *(float2*)(out + rb + off) = v;
        }
    }
}

// ---------------------------------------------------------------------------
extern "C" void kernel_launch(void* const* d_in, const int* in_sizes, int n_in,
                              void* d_out, int out_size)
{
    const float* x     = (const float*)d_in[0];
    const float* wconv = (const float*)d_in[1];
    const float* w1    = (const float*)d_in[2];
    const float* b1    = (const float*)d_in[3];
    const float* gamma = (const float*)d_in[4];
    const float* beta  = (const float*)d_in[5];
    const float* mean  = (const float*)d_in[6];
    const float* var   = (const float*)d_in[7];
    float* out = (float*)d_out;

    static bool attr_done = false;
    if (!attr_done) {
        cudaFuncSetAttribute(k_conv3, cudaFuncAttributeMaxDynamicSharedMemorySize, DSMEM_BYTES);
        cudaFuncSetAttribute(k_pw,    cudaFuncAttributeMaxDynamicSharedMemorySize, DSMEM_BYTES);
        attr_done = true;
    }

    k_repack_conv<<<(C2 * C1 * 9 + 255) / 256, 256>>>(wconv);
    k_repack_pw  <<<(C2 * C2 + 255) / 256, 256>>>(w1);
    k_prep_x     <<<(int)(XVSZ / 8 / 256), 256>>>(x);
    k_zero_sh    <<<(4 * 16 * 64 * 128 + 255) / 256, 256>>>();

    dim3 grid(H_, 2, B_);   // 128 rows x 2 oc-halves x 16 batch = 4096 CTAs
    k_conv3<<<grid, NTHR, DSMEM_BYTES>>>(gamma, beta, mean, var);
    k_pw   <<<grid, NTHR, DSMEM_BYTES>>>(b1, gamma, beta, mean, var, out);
}

// round 12
// speedup vs baseline: 1.1265x; 1.1265x over previous
#include <cuda_runtime.h>
#include <cuda_fp16.h>

// SConv R11: 3 CTAs/SM (24 warps/SM). CTA 128oc x 64px, 8 warps 4Mx2N,
// warp 32x32, acc 32 regs. K=32 chunks, 4-stage cp.async ring (12KB/stage).
// mma.sync m16n8k16 fp16; shifts pre-applied in gmem (same buffers as R9).

#define B_  16
#define C1  128
#define C2  256
#define H_  128
#define W_  128
#define HW  (H_*W_)
#define EPSBN 1e-5f

typedef unsigned int uint;

#define XVSZ ((size_t)B_ * C1 * HW)

__device__ __half g_xv [3 * XVSZ];                // x fp16, col-shift variants -1/0/+1
__device__ __half g_yi [(size_t)B_ * C2 * HW];    // y fp16 plain (identity)
__device__ __half g_ysh[(size_t)B_ * C2 * HW];    // y fp16 pre-shifted per group
__device__ __half g_wA16[36 * 2 * 4096];          // conv w, frag order
__device__ __half g_wB16[ 8 * 2 * 4096];          // 1x1 w, frag order

__device__ __forceinline__ float silu_f(float v) { return v / (1.0f + __expf(-v)); }
__device__ __forceinline__ uint smem_u32(const void* p) {
    uint a;
    asm("{ .reg .u64 t; cvta.to.shared.u64 t, %1; cvt.u32.u64 %0, t; }" : "=r"(a) : "l"(p));
    return a;
}

#define MMA16(d, a, b0v, b1v) \
    asm volatile("mma.sync.aligned.m16n8k16.row.col.f32.f16.f16.f32 " \
        "{%0,%1,%2,%3}, {%4,%5,%6,%7}, {%8,%9}, {%0,%1,%2,%3};" \
        : "+f"((d)[0]), "+f"((d)[1]), "+f"((d)[2]), "+f"((d)[3]) \
        : "r"((a).x), "r"((a).y), "r"((a).z), "r"((a).w), "r"(b0v), "r"(b1v))

#define CP_A16(sm, gp) \
    asm volatile("cp.async.cg.shared.global [%0], [%1], 16;" :: "r"(sm), "l"(gp))
#define CP_A16Z(sm, gp, sz) \
    asm volatile("cp.async.cg.shared.global [%0], [%1], 16, %2;" :: "r"(sm), "l"(gp), "r"(sz))
#define CP_COMMIT() asm volatile("cp.async.commit_group;")
#define CP_WAIT2()  asm volatile("cp.async.wait_group 2;" ::: "memory")
#define CP_WAIT0()  asm volatile("cp.async.wait_group 0;" ::: "memory")

// Chunk (K=32): A 8192 B (128oc, frag order) + B 4096 B ([kk 32][n 64],
// 128B rows, 16B-granule XOR swizzle: granule (kk,g) at kk*128 + ((g^(kk&7))<<4)).
#define A_BYTES 8192
#define B_BYTES 4096
#define STAGE   (A_BYTES + B_BYTES)   // 12288
#define NSTG    4
#define DSMEM_BYTES (NSTG * STAGE)    // 49152 per CTA, 3 CTAs/SM

#define NTHR 256

// --------------------------------------------------------- repack kernels --
__device__ __forceinline__ int fragoff(int m, int kk) {
    return (((kk >> 4) * 8 + (m >> 4)) * 32 + (((m & 7) << 2) | ((kk >> 1) & 3))) * 8
         + (((kk >> 3) & 1) * 2 + ((m >> 3) & 1)) * 2 + (kk & 1);
}
__global__ __launch_bounds__(256) void k_repack_conv(const float* __restrict__ wc) {
    int idx = blockIdx.x * 256 + threadIdx.x;
    if (idx >= C2 * C1 * 9) return;
    int tap = idx % 9, rest = idx / 9;
    int ic = rest % C1, oc = rest / C1;
    int it = (ic >> 5) * 9 + tap;
    g_wA16[(size_t)(it * 2 + (oc >> 7)) * 4096 + fragoff(oc & 127, ic & 31)] =
        __float2half_rn(wc[idx]);
}
__global__ __launch_bounds__(256) void k_repack_pw(const float* __restrict__ w1) {
    int idx = blockIdx.x * 256 + threadIdx.x;
    if (idx >= C2 * C2) return;
    int ic = idx % C2, oc = idx / C2;
    g_wB16[(size_t)((ic >> 5) * 2 + (oc >> 7)) * 4096 + fragoff(oc & 127, ic & 31)] =
        __float2half_rn(w1[idx]);
}

__global__ __launch_bounds__(256) void k_prep_x(const float* __restrict__ x) {
    size_t i = (size_t)blockIdx.x * 256 + threadIdx.x;   // over XVSZ/8
    size_t base = i * 8;
    int w0 = (int)(base & 127);
    const float* p = x + base;
    float4 a  = __ldg((const float4*)p);
    float4 b4 = __ldg((const float4*)(p + 4));
    float xm1 = (w0 > 0)   ? __ldg(p - 1) : 0.f;
    float xp8 = (w0 < 120) ? __ldg(p + 8) : 0.f;
    __half2* v0 = (__half2*)g_xv + i * 4;
    __half2* v1 = (__half2*)(g_xv + XVSZ) + i * 4;
    __half2* v2 = (__half2*)(g_xv + 2 * XVSZ) + i * 4;
    v1[0] = __floats2half2_rn(a.x, a.y);  v1[1] = __floats2half2_rn(a.z, a.w);
    v1[2] = __floats2half2_rn(b4.x, b4.y); v1[3] = __floats2half2_rn(b4.z, b4.w);
    v0[0] = __floats2half2_rn(xm1, a.x);  v0[1] = __floats2half2_rn(a.y, a.z);
    v0[2] = __floats2half2_rn(a.w, b4.x); v0[3] = __floats2half2_rn(b4.y, b4.z);
    v2[0] = __floats2half2_rn(a.y, a.z);  v2[1] = __floats2half2_rn(a.w, b4.x);
    v2[2] = __floats2half2_rn(b4.y, b4.z); v2[3] = __floats2half2_rn(b4.w, xp8);
}

__global__ __launch_bounds__(256) void k_zero_sh() {
    int idx = blockIdx.x * 256 + threadIdx.x;   // 524288
    if (idx >= 4 * 16 * 64 * 128) return;
    int grp = idx >> 17, r = idx & 131071;
    int b = r >> 13, r2 = r & 8191;
    int c = r2 >> 7, p = r2 & 127;
    int oc, h, w;
    if      (grp == 0) { oc = c;       h = p;   w = 0;   }
    else if (grp == 1) { oc = 64 + c;  h = 127; w = p;   }
    else if (grp == 2) { oc = 128 + c; h = p;   w = 127; }
    else               { oc = 192 + c; h = 0;   w = p;   }
    g_ysh[(((size_t)b * C2 + oc) << 14) + h * W_ + w] = __float2half_rn(0.f);
}

// --------------------------------------------------------- staging helpers --
// A chunk 8192 B, 256 thr -> 2 x 16B per thread.
__device__ __forceinline__ void cp_issue_A(uint Asm, const __half* src, int tid) {
    const char* g = (const char*)src;
    CP_A16(Asm + tid * 16, g + tid * 16);
    CP_A16(Asm + 4096 + tid * 16, g + 4096 + tid * 16);
}
// B chunk 4096 B: thread owns granule g (=tid&7), row kk (=tid>>3, 0..31).
__device__ __forceinline__ void cp_issue_B(uint Bsm, const __half* vbase,
                                           int kk, uint gxor, int hs, int wcol) {
    uint ok = ((uint)hs < 128u) ? 16u : 0u;
    int hsc = (hs < 0) ? 0 : (hs > 127 ? 127 : hs);
    const char* s = (const char*)(vbase + (size_t)kk * HW + hsc * W_ + wcol);
    CP_A16Z(Bsm + kk * 128 + gxor, s, ok);
}

// ----------------------------------------------------------------- MMA -----
// warp tile 32oc x 32px: wm=wrp>>1 (0..3), wn=wrp&1. mf 0..1, nf 0..3.
__device__ __forceinline__ void mma_chunk(uint Asm, uint Bsm, int wm, int wn,
                                          int lane, float acc[2][4][4]) {
    const int j = lane >> 3, r = lane & 7;
    const int jk = (j & 1) << 3, jn = j >> 1;
#pragma unroll
    for (int ks = 0; ks < 2; ++ks) {
        uint4 a[2];
#pragma unroll
        for (int mf = 0; mf < 2; ++mf) {
            uint ad = Asm + (((ks * 8 + wm * 2 + mf) * 32 + lane) << 4);
            asm volatile("ld.shared.v4.b32 {%0,%1,%2,%3}, [%4];"
                : "=r"(a[mf].x), "=r"(a[mf].y), "=r"(a[mf].z), "=r"(a[mf].w) : "r"(ad));
        }
        uint bf[4][2];
#pragma unroll
        for (int p = 0; p < 2; ++p) {
            int krow = ks * 16 + jk + r;
            int oct  = wn * 4 + 2 * p + jn;
            uint ad = Bsm + krow * 128 + ((uint)(oct ^ (krow & 7)) << 4);
            uint d0, d1, d2, d3;
            asm volatile("ldmatrix.sync.aligned.m8n8.x4.trans.shared.b16 "
                "{%0,%1,%2,%3}, [%4];"
                : "=r"(d0), "=r"(d1), "=r"(d2), "=r"(d3) : "r"(ad));
            bf[2 * p][0] = d0; bf[2 * p][1] = d1;
            bf[2 * p + 1][0] = d2; bf[2 * p + 1][1] = d3;
        }
#pragma unroll
        for (int mf = 0; mf < 2; ++mf)
#pragma unroll
            for (int nf = 0; nf < 4; ++nf)
                MMA16(acc[mf][nf], a[mf], bf[nf][0], bf[nf][1]);
    }
}

// ------------------------------------------------------ conv3x3 + BN + SiLU
__global__ __launch_bounds__(NTHR, 3) void k_conv3(
    const float* __restrict__ gamma, const float* __restrict__ beta,
    const float* __restrict__ mean,  const float* __restrict__ var)
{
    extern __shared__ __align__(16) char dsm[];
    const uint smb = smem_u32(dsm);

    const int tid = threadIdx.x;
    const int wrp = tid >> 5, lane = tid & 31;
    const int wm = wrp >> 1, wn = wrp & 1;
    const int kkB = tid >> 3, gB = tid & 7;
    const uint gxor = ((uint)(gB ^ (kkB & 7))) << 4;
    const int h0  = blockIdx.x >> 1;
    const int w0c = (blockIdx.x & 1) * 64;
    const int ocg = blockIdx.y, oc0 = ocg * 128;
    const int b   = blockIdx.z;
    const int wcol = w0c + gB * 8;

    float acc[2][4][4];
#pragma unroll
    for (int i = 0; i < 2; ++i)
#pragma unroll
        for (int jj = 0; jj < 4; ++jj)
#pragma unroll
            for (int q = 0; q < 4; ++q) acc[i][jj][q] = 0.0f;

    const size_t bofs = (size_t)b * C1 * HW;
#define ISSUE_CONV(nit, s) do { \
        int kc_ = (nit) / 9, tap_ = (nit) - 9 * kc_; \
        int ky_ = tap_ / 3, kx_ = tap_ - 3 * ky_; \
        cp_issue_A(smb + (s) * STAGE, g_wA16 + (size_t)((nit) * 2 + ocg) * 4096, tid); \
        const __half* vb_ = g_xv + (size_t)kx_ * XVSZ + bofs + (size_t)kc_ * 32 * HW; \
        cp_issue_B(smb + (s) * STAGE + A_BYTES, vb_, kkB, gxor, h0 + ky_ - 1, wcol); \
        CP_COMMIT(); \
    } while (0)

    ISSUE_CONV(0, 0);
    ISSUE_CONV(1, 1);
    ISSUE_CONV(2, 2);

#pragma unroll 1
    for (int st = 0; st < 36; ++st) {
        if (st + 3 < 36) CP_WAIT2(); else CP_WAIT0();
        __syncthreads();
        if (st + 3 < 36) {
            int s = (st + 3) & 3;
            ISSUE_CONV(st + 3, s);
        }
        const uint sb = smb + (st & 3) * STAGE;
        mma_chunk(sb, sb + A_BYTES, wm, wn, lane, acc);
        __syncthreads();
    }
#undef ISSUE_CONV

    // epilogue: BN + SiLU -> g_yi (plain) + g_ysh (shifted by group)
    const int grp = ((oc0 + wm * 32) >> 6) & 3;   // warp-uniform
    const int h = h0;
#pragma unroll
    for (int mf = 0; mf < 2; ++mf) {
        const int oc_a = oc0 + wm * 32 + mf * 16 + (lane >> 2);
        const int oc_b = oc_a + 8;
        const float inva = __ldg(&gamma[oc_a]) * rsqrtf(__ldg(&var[oc_a]) + EPSBN);
        const float bba  = __ldg(&beta[oc_a]) - __ldg(&mean[oc_a]) * inva;
        const float invb = __ldg(&gamma[oc_b]) * rsqrtf(__ldg(&var[oc_b]) + EPSBN);
        const float bbb  = __ldg(&beta[oc_b]) - __ldg(&mean[oc_b]) * invb;
        const size_t ra = ((size_t)b * C2 + oc_a) * HW;
        const size_t rb = ((size_t)b * C2 + oc_b) * HW;
#pragma unroll
        for (int nf = 0; nf < 4; ++nf) {
            const int w = w0c + wn * 32 + nf * 8 + (lane & 3) * 2;
            const int off = h * W_ + w;
            float2 u, v;
            u.x = silu_f(acc[mf][nf][0] * inva + bba);
            u.y = silu_f(acc[mf][nf][1] * inva + bba);
            v.x = silu_f(acc[mf][nf][2] * invb + bbb);
            v.y = silu_f(acc[mf][nf][3] * invb + bbb);
            __half2 uh = __floats2half2_rn(u.x, u.y);
            __half2 vh = __floats2half2_rn(v.x, v.y);
            *(__half2*)(g_yi + ra + off) = uh;
            *(__half2*)(g_yi + rb + off) = vh;
            if (grp == 0) {            // dest (h, w+1)
                g_ysh[ra + off + 1] = __low2half(uh);
                g_ysh[rb + off + 1] = __low2half(vh);
                if (w < 126) {
                    g_ysh[ra + off + 2] = __high2half(uh);
                    g_ysh[rb + off + 2] = __high2half(vh);
                }
            } else if (grp == 1) {     // dest (h-1, w)
                if (h > 0) {
                    *(__half2*)(g_ysh + ra + off - W_) = uh;
                    *(__half2*)(g_ysh + rb + off - W_) = vh;
                }
            } else if (grp == 2) {     // dest (h, w-1)
                if (w > 0) {
                    g_ysh[ra + off - 1] = __low2half(uh);
                    g_ysh[rb + off - 1] = __low2half(vh);
                }
                g_ysh[ra + off] = __high2half(uh);
                g_ysh[rb + off] = __high2half(vh);
            } else {                   // dest (h+1, w)
                if (h < 127) {
                    *(__half2*)(g_ysh + ra + off + W_) = uh;
                    *(__half2*)(g_ysh + rb + off + W_) = vh;
                }
            }
        }
    }
}

// --------------------------- conv1x1(shifted y) + bias + BN + id + SiLU ----
__global__ __launch_bounds__(NTHR, 3) void k_pw(
    const float* __restrict__ b1,
    const float* __restrict__ gamma, const float* __restrict__ beta,
    const float* __restrict__ mean,  const float* __restrict__ var,
    float* __restrict__ out)
{
    extern __shared__ __align__(16) char dsm[];
    const uint smb = smem_u32(dsm);

    const int tid = threadIdx.x;
    const int wrp = tid >> 5, lane = tid & 31;
    const int wm = wrp >> 1, wn = wrp & 1;
    const int kkB = tid >> 3, gB = tid & 7;
    const uint gxor = ((uint)(gB ^ (kkB & 7))) << 4;
    const int h0  = blockIdx.x >> 1;
    const int w0c = (blockIdx.x & 1) * 64;
    const int ocg = blockIdx.y, oc0 = ocg * 128;
    const int b   = blockIdx.z;
    const int wcol = w0c + gB * 8;

    float acc[2][4][4];
#pragma unroll
    for (int i = 0; i < 2; ++i)
#pragma unroll
        for (int jj = 0; jj < 4; ++jj)
#pragma unroll
            for (int q = 0; q < 4; ++q) acc[i][jj][q] = 0.0f;

    const size_t bofs = (size_t)b * C2 * HW;
#define ISSUE_PW(nit, s) do { \
        cp_issue_A(smb + (s) * STAGE, g_wB16 + (size_t)((nit) * 2 + ocg) * 4096, tid); \
        const __half* vb_ = g_ysh + bofs + (size_t)(nit) * 32 * HW; \
        cp_issue_B(smb + (s) * STAGE + A_BYTES, vb_, kkB, gxor, h0, wcol); \
        CP_COMMIT(); \
    } while (0)

    ISSUE_PW(0, 0);
    ISSUE_PW(1, 1);
    ISSUE_PW(2, 2);

#pragma unroll 1
    for (int st = 0; st < 8; ++st) {
        if (st + 3 < 8) CP_WAIT2(); else CP_WAIT0();
        __syncthreads();
        if (st + 3 < 8) {
            int s = (st + 3) & 3;
            ISSUE_PW(st + 3, s);
        }
        const uint sb = smb + (st & 3) * STAGE;
        mma_chunk(sb, sb + A_BYTES, wm, wn, lane, acc);
        __syncthreads();
    }
#undef ISSUE_PW

    // epilogue: +bias, BN, +identity(fp16), SiLU -> out (fp32)
    const int h = h0;
#pragma unroll
    for (int mf = 0; mf < 2; ++mf) {
        const int oc_a = oc0 + wm * 32 + mf * 16 + (lane >> 2);
        const int oc_b = oc_a + 8;
        const float inva = __ldg(&gamma[oc_a]) * rsqrtf(__ldg(&var[oc_a]) + EPSBN);
        const float bba  = __ldg(&beta[oc_a]) - __ldg(&mean[oc_a]) * inva;
        const float bsa  = __ldg(&b1[oc_a]);
        const float invb = __ldg(&gamma[oc_b]) * rsqrtf(__ldg(&var[oc_b]) + EPSBN);
        const float bbb  = __ldg(&beta[oc_b]) - __ldg(&mean[oc_b]) * invb;
        const float bsb  = __ldg(&b1[oc_b]);
        const size_t ra = ((size_t)b * C2 + oc_a) * HW;
        const size_t rb = ((size_t)b * C2 + oc_b) * HW;
#pragma unroll
        for (int nf = 0; nf < 4; ++nf) {
            const int w = w0c + wn * 32 + nf * 8 + (lane & 3) * 2;
            const int off = h * W_ + w;
            float2 ida = __half22float2(*(const __half2*)(g_yi + ra + off));
            float2 idb = __half22float2(*(const __half2*)(g_yi + rb + off));
            float2 u, v; float z;
            z = (acc[mf][nf][0] + bsa) * inva + bba + ida.x; u.x = silu_f(z);
            z = (acc[mf][nf][1] + bsa) * inva + bba + ida.y; u.y = silu_f(z);
            z = (acc[mf][nf][2] + bsb) * invb + bbb + idb.x; v.x = silu_f(z);
            z = (acc[mf][nf][3] + bsb) * invb + bbb + idb.y; v.y = silu_f(z);
            *(float2*)(out + ra + off) = u;
            *(float2*)(out + rb + off) = v;
        }
    }
}

// ---------------------------------------------------------------------------
extern "C" void kernel_launch(void* const* d_in, const int* in_sizes, int n_in,
                              void* d_out, int out_size)
{
    const float* x     = (const float*)d_in[0];
    const float* wconv = (const float*)d_in[1];
    const float* w1    = (const float*)d_in[2];
    const float* b1    = (const float*)d_in[3];
    const float* gamma = (const float*)d_in[4];
    const float* beta  = (const float*)d_in[5];
    const float* mean  = (const float*)d_in[6];
    const float* var   = (const float*)d_in[7];
    float* out = (float*)d_out;

    static bool attr_done = false;
    if (!attr_done) {
        cudaFuncSetAttribute(k_conv3, cudaFuncAttributeMaxDynamicSharedMemorySize, DSMEM_BYTES);
        cudaFuncSetAttribute(k_pw,    cudaFuncAttributeMaxDynamicSharedMemorySize, DSMEM_BYTES);
        attr_done = true;
    }

    k_repack_conv<<<(C2 * C1 * 9 + 255) / 256, 256>>>(wconv);
    k_repack_pw  <<<(C2 * C2 + 255) / 256, 256>>>(w1);
    k_prep_x     <<<(int)(XVSZ / 8 / 256), 256>>>(x);
    k_zero_sh    <<<(4 * 16 * 64 * 128 + 255) / 256, 256>>>();

    dim3 grid(2 * H_, 2, B_);   // 256 (row,half) x 2 ocg x 16 batch = 8192 CTAs
    k_conv3<<<grid, NTHR, DSMEM_BYTES>>>(gamma, beta, mean, var);
    k_pw   <<<grid, NTHR, DSMEM_BYTES>>>(b1, gamma, beta, mean, var, out);
}

// round 13
// speedup vs baseline: 1.1794x; 1.0470x over previous
#include <cuda_runtime.h>
#include <cuda_fp16.h>

// SConv R12: R9 GEMM cores with cp.async.bulk staging (1 instr / 8KB tile).
// All tiles pre-swizzled & contiguous in gmem; mbarrier-completed 4-stage ring.
// CTA: 256 thr (8 warps 4Mx2N, warp 32x64), tile 128oc x 128px, 2 CTAs/SM.

#define B_  16
#define C1  128
#define C2  256
#define H_  128
#define W_  128
#define HW  (H_*W_)
#define EPSBN 1e-5f

typedef unsigned int uint;

// x tiles: [kx 3][b 16][hp 130][kc 4] blocks of 8KB (32ch x 128w fp16, swizzled)
__device__ __half g_xs[(size_t)3 * B_ * 130 * 4 * 4096];
// y shifted tiles (pw B operand): [b][h 128][kc 8] blocks of 8KB, swizzled
__device__ __half g_ys[(size_t)B_ * 128 * 8 * 4096];
__device__ __half g_yi [(size_t)B_ * C2 * HW];    // y fp16 plain (identity)
__device__ __half g_wA16[36 * 2 * 4096];          // conv w, frag order
__device__ __half g_wB16[ 8 * 2 * 4096];          // 1x1 w, frag order

__device__ __forceinline__ float silu_f(float v) { return v / (1.0f + __expf(-v)); }
__device__ __forceinline__ uint smem_u32(const void* p) {
    uint a;
    asm("{ .reg .u64 t; cvta.to.shared.u64 t, %1; cvt.u32.u64 %0, t; }" : "=r"(a) : "l"(p));
    return a;
}

#define MMA16(d, a, b0v, b1v) \
    asm volatile("mma.sync.aligned.m16n8k16.row.col.f32.f16.f16.f32 " \
        "{%0,%1,%2,%3}, {%4,%5,%6,%7}, {%8,%9}, {%0,%1,%2,%3};" \
        : "+f"((d)[0]), "+f"((d)[1]), "+f"((d)[2]), "+f"((d)[3]) \
        : "r"((a).x), "r"((a).y), "r"((a).z), "r"((a).w), "r"(b0v), "r"(b1v))

#define MBAR_INIT(a, c) \
    asm volatile("mbarrier.init.shared.b64 [%0], %1;" :: "r"(a), "r"(c) : "memory")
#define MBAR_EXPECT(a, by) \
    asm volatile("mbarrier.arrive.expect_tx.shared.b64 _, [%0], %1;" :: "r"(a), "r"(by) : "memory")
#define BULK_G2S(dst, src, sz, mb) \
    asm volatile("cp.async.bulk.shared::cta.global.mbarrier::complete_tx::bytes [%0], [%1], %2, [%3];" \
        :: "r"(dst), "l"(src), "r"(sz), "r"(mb) : "memory")
__device__ __forceinline__ void mbar_wait(uint a, uint ph) {
    asm volatile(
        "{\n\t.reg .pred P;\n\tWL%=:\n\t"
        "mbarrier.try_wait.parity.shared.b64 P, [%0], %1;\n\t"
        "@!P bra WL%=;\n\t}" :: "r"(a), "r"(ph) : "memory");
}

// Chunk (K=32): A 8192 B (128oc frag order) + B 8192 B ([kk 32][n 128],
// 256B rows, 16B-granule XOR swizzle: granule (kk,g) at kk*256 + ((g^(kk&7))<<4)).
#define A_BYTES 8192
#define B_BYTES 8192
#define STAGE   (A_BYTES + B_BYTES)   // 16384
#define NSTG    4
#define DSMEM_BYTES (NSTG * STAGE)    // 65536 per CTA, 2 CTAs/SM

#define NTHR 256

// swizzled byte offset of (kk, w) inside an 8KB B tile
__device__ __forceinline__ int ysoff(int kk, int wp) {
    return kk * 256 + ((((wp >> 3) ^ (kk & 7))) << 4) + (wp & 7) * 2;
}

// --------------------------------------------------------- repack kernels --
__device__ __forceinline__ int fragoff(int m, int kk) {
    return (((kk >> 4) * 8 + (m >> 4)) * 32 + (((m & 7) << 2) | ((kk >> 1) & 3))) * 8
         + (((kk >> 3) & 1) * 2 + ((m >> 3) & 1)) * 2 + (kk & 1);
}
__global__ __launch_bounds__(256) void k_repack_conv(const float* __restrict__ wc) {
    int idx = blockIdx.x * 256 + threadIdx.x;
    if (idx >= C2 * C1 * 9) return;
    int tap = idx % 9, rest = idx / 9;
    int ic = rest % C1, oc = rest / C1;
    int it = (ic >> 5) * 9 + tap;
    g_wA16[(size_t)(it * 2 + (oc >> 7)) * 4096 + fragoff(oc & 127, ic & 31)] =
        __float2half_rn(wc[idx]);
}
__global__ __launch_bounds__(256) void k_repack_pw(const float* __restrict__ w1) {
    int idx = blockIdx.x * 256 + threadIdx.x;
    if (idx >= C2 * C2) return;
    int ic = idx % C2, oc = idx / C2;
    g_wB16[(size_t)((ic >> 5) * 2 + (oc >> 7)) * 4096 + fragoff(oc & 127, ic & 31)] =
        __float2half_rn(w1[idx]);
}

// x fp32 -> 3 column-shift variants, swizzled 8KB tiles, halo rows at hp 0/129
__global__ __launch_bounds__(256) void k_prep_x(const float* __restrict__ x) {
    const int h = blockIdx.x, b = blockIdx.y;
    const int tid = threadIdx.x;
#pragma unroll
    for (int i = 0; i < 8; ++i) {
        int item = tid + i * 256;            // 0..2047
        int kc = item >> 9, r = item & 511;
        int kk = r >> 4, g = r & 15;
        const float* src = x + (((size_t)(b * C1 + kc * 32 + kk)) * H_ + h) * W_;
        int w0 = g * 8;
        float v[10];
#pragma unroll
        for (int j = 0; j < 10; ++j) {
            int gw = w0 - 1 + j;
            v[j] = ((uint)gw < 128u) ? __ldg(src + gw) : 0.f;
        }
        uint off = (uint)(kk * 256 + ((g ^ (kk & 7)) << 4));
#pragma unroll
        for (int kx = 0; kx < 3; ++kx) {
            __align__(16) __half hh[8];
#pragma unroll
            for (int j = 0; j < 8; ++j) hh[j] = __float2half_rn(v[j + kx]);
            size_t blk = ((size_t)(kx * B_ + b) * 130 + (h + 1)) * 4 + kc;
            *(uint4*)((char*)g_xs + blk * 8192 + off) = *(const uint4*)hh;
        }
    }
}

// zero x halo rows (hp = 0, 129)
__global__ __launch_bounds__(256) void k_zero_xs() {
    int i = blockIdx.x;                       // 384 blocks
    int kx = i % 3, rest = i / 3;
    int b = rest % 16; rest /= 16;
    int e = rest % 2, kc = rest / 2;
    size_t blk = ((size_t)(kx * B_ + b) * 130 + (e ? 129 : 0)) * 4 + kc;
    uint4* p = (uint4*)((char*)g_xs + blk * 8192);
    p[threadIdx.x * 2]     = make_uint4(0, 0, 0, 0);
    p[threadIdx.x * 2 + 1] = make_uint4(0, 0, 0, 0);
}

// zero g_ys borders: col w'=0 (kc 0,1) and w'=127 (kc 4,5)
__global__ __launch_bounds__(256) void k_zero_ys() {
    int idx = blockIdx.x * 256 + threadIdx.x;     // 262144
    if (idx >= 262144) return;
    int sel = idx >> 17, r = idx & 131071;
    int b = r >> 13, r2 = r & 8191;
    int hh = r2 >> 6, r3 = r2 & 63;
    int kc2 = r3 >> 5, kk = r3 & 31;
    int kc, wp;
    if (sel == 0) { kc = kc2;     wp = 0;   }
    else          { kc = 4 + kc2; wp = 127; }
    size_t blk = ((size_t)(b * 128 + hh) * 8 + kc);
    *(__half*)((char*)g_ys + blk * 8192 + ysoff(kk, wp)) = __float2half_rn(0.f);
}
// zero g_ys full border blocks: kc 2,3 @ h=127 ; kc 6,7 @ h=0
__global__ __launch_bounds__(256) void k_zero_ys_blk() {
    int i = blockIdx.x;                        // 64 blocks
    int b = i >> 2, q = i & 3;
    int kc = (q < 2) ? 2 + q : 6 + (q - 2);
    int hh = (q < 2) ? 127 : 0;
    size_t blk = ((size_t)(b * 128 + hh) * 8 + kc);
    uint4* p = (uint4*)((char*)g_ys + blk * 8192);
    p[threadIdx.x * 2]     = make_uint4(0, 0, 0, 0);
    p[threadIdx.x * 2 + 1] = make_uint4(0, 0, 0, 0);
}

// ----------------------------------------------------------------- MMA -----
// warp tile 32oc x 64px: wm=wrp>>1 (0..3), wn=wrp&1. mf 0..1, nf 0..7.
__device__ __forceinline__ void mma_chunk(uint Asm, uint Bsm, int wm, int wn,
                                          int lane, float acc[2][8][4]) {
    const int j = lane >> 3, r = lane & 7;
    const int jk = (j & 1) << 3, jn = j >> 1;
#pragma unroll
    for (int ks = 0; ks < 2; ++ks) {
        uint4 a[2];
#pragma unroll
        for (int mf = 0; mf < 2; ++mf) {
            uint ad = Asm + (((ks * 8 + wm * 2 + mf) * 32 + lane) << 4);
            asm volatile("ld.shared.v4.b32 {%0,%1,%2,%3}, [%4];"
                : "=r"(a[mf].x), "=r"(a[mf].y), "=r"(a[mf].z), "=r"(a[mf].w) : "r"(ad));
        }
        uint bf[8][2];
#pragma unroll
        for (int p = 0; p < 4; ++p) {
            int krow = ks * 16 + jk + r;
            int oct  = wn * 8 + 2 * p + jn;
            uint ad = Bsm + krow * 256 + ((uint)(oct ^ (krow & 7)) << 4);
            uint d0, d1, d2, d3;
            asm volatile("ldmatrix.sync.aligned.m8n8.x4.trans.shared.b16 "
                "{%0,%1,%2,%3}, [%4];"
                : "=r"(d0), "=r"(d1), "=r"(d2), "=r"(d3) : "r"(ad));
            bf[2 * p][0] = d0; bf[2 * p][1] = d1;
            bf[2 * p + 1][0] = d2; bf[2 * p + 1][1] = d3;
        }
#pragma unroll
        for (int mf = 0; mf < 2; ++mf)
#pragma unroll
            for (int nf = 0; nf < 8; ++nf)
                MMA16(acc[mf][nf], a[mf], bf[nf][0], bf[nf][1]);
    }
}

// ------------------------------------------------------ conv3x3 + BN + SiLU
__global__ __launch_bounds__(NTHR, 2) void k_conv3(
    const float* __restrict__ gamma, const float* __restrict__ beta,
    const float* __restrict__ mean,  const float* __restrict__ var)
{
    extern __shared__ __align__(16) char dsm[];
    __shared__ __align__(8) unsigned long long s_mb[NSTG];
    const uint smb = smem_u32(dsm);
    const uint mbb = smem_u32(&s_mb[0]);

    const int tid = threadIdx.x;
    const int wrp = tid >> 5, lane = tid & 31;
    const int wm = wrp >> 1, wn = wrp & 1;
    const int h0  = blockIdx.x;
    const int ocg = blockIdx.y, oc0 = ocg * 128;
    const int b   = blockIdx.z;

    if (tid < NSTG) MBAR_INIT(mbb + tid * 8, 1);
    __syncthreads();

    float acc[2][8][4];
#pragma unroll
    for (int i = 0; i < 2; ++i)
#pragma unroll
        for (int jj = 0; jj < 8; ++jj)
#pragma unroll
            for (int q = 0; q < 4; ++q) acc[i][jj][q] = 0.0f;

#define ISSUE_CONV(nit, s) do { \
        int kc_ = (nit) / 9, tap_ = (nit) - 9 * kc_; \
        int ky_ = tap_ / 3, kx_ = tap_ - 3 * ky_; \
        uint mbx = mbb + (s) * 8; \
        MBAR_EXPECT(mbx, 16384u); \
        BULK_G2S(smb + (s) * STAGE, \
                 (const char*)g_wA16 + (size_t)((nit) * 2 + ocg) * 8192, 8192u, mbx); \
        size_t blk_ = ((size_t)(kx_ * B_ + b) * 130 + (h0 + ky_)) * 4 + kc_; \
        BULK_G2S(smb + (s) * STAGE + A_BYTES, \
                 (const char*)g_xs + blk_ * 8192, 8192u, mbx); \
    } while (0)

    if (tid == 0) { ISSUE_CONV(0, 0); ISSUE_CONV(1, 1); ISSUE_CONV(2, 2); }

#pragma unroll 1
    for (int it = 0; it < 36; ++it) {
        mbar_wait(mbb + (it & 3) * 8, (uint)((it >> 2) & 1));
        const uint sb = smb + (it & 3) * STAGE;
        mma_chunk(sb, sb + A_BYTES, wm, wn, lane, acc);
        __syncthreads();
        if (tid == 0 && it + 3 < 36) ISSUE_CONV(it + 3, (it + 3) & 3);
    }
#undef ISSUE_CONV

    // epilogue: BN + SiLU -> g_yi (linear) + g_ys (shifted, swizzled tiles)
    const int kcg = (oc0 >> 5) + wm;          // global kc of this warp's 32 oc
    const int grp = (kcg >> 1) & 3;
    const int h = h0;
#pragma unroll
    for (int mf = 0; mf < 2; ++mf) {
        const int kk_a = mf * 16 + (lane >> 2), kk_b = kk_a + 8;
        const int oc_a = kcg * 32 + kk_a, oc_b = oc_a + 8;
        const float inva = __ldg(&gamma[oc_a]) * rsqrtf(__ldg(&var[oc_a]) + EPSBN);
        const float bba  = __ldg(&beta[oc_a]) - __ldg(&mean[oc_a]) * inva;
        const float invb = __ldg(&gamma[oc_b]) * rsqrtf(__ldg(&var[oc_b]) + EPSBN);
        const float bbb  = __ldg(&beta[oc_b]) - __ldg(&mean[oc_b]) * invb;
        const size_t ra = ((size_t)b * C2 + oc_a) * HW;
        const size_t rb = ((size_t)b * C2 + oc_b) * HW;
#pragma unroll
        for (int nf = 0; nf < 8; ++nf) {
            const int w = wn * 64 + nf * 8 + (lane & 3) * 2;
            const int off = h * W_ + w;
            float2 u, v;
            u.x = silu_f(acc[mf][nf][0] * inva + bba);
            u.y = silu_f(acc[mf][nf][1] * inva + bba);
            v.x = silu_f(acc[mf][nf][2] * invb + bbb);
            v.y = silu_f(acc[mf][nf][3] * invb + bbb);
            __half2 uh = __floats2half2_rn(u.x, u.y);
            __half2 vh = __floats2half2_rn(v.x, v.y);
            *(__half2*)(g_yi + ra + off) = uh;
            *(__half2*)(g_yi + rb + off) = vh;
            if (grp == 1) {                   // dest (h-1, w)
                if (h > 0) {
                    char* ysb = (char*)g_ys + ((size_t)(b * 128 + h - 1) * 8 + kcg) * 8192;
                    *(__half2*)(ysb + ysoff(kk_a, w)) = uh;
                    *(__half2*)(ysb + ysoff(kk_b, w)) = vh;
                }
            } else if (grp == 3) {            // dest (h+1, w)
                if (h < 127) {
                    char* ysb = (char*)g_ys + ((size_t)(b * 128 + h + 1) * 8 + kcg) * 8192;
                    *(__half2*)(ysb + ysoff(kk_a, w)) = uh;
                    *(__half2*)(ysb + ysoff(kk_b, w)) = vh;
                }
            } else if (grp == 0) {            // dest (h, w+1)
                char* ysb = (char*)g_ys + ((size_t)(b * 128 + h) * 8 + kcg) * 8192;
                *(__half*)(ysb + ysoff(kk_a, w + 1)) = __low2half(uh);
                *(__half*)(ysb + ysoff(kk_b, w + 1)) = __low2half(vh);
                if (w < 126) {
                    *(__half*)(ysb + ysoff(kk_a, w + 2)) = __high2half(uh);
                    *(__half*)(ysb + ysoff(kk_b, w + 2)) = __high2half(vh);
                }
            } else {                          // grp 2: dest (h, w-1)
                char* ysb = (char*)g_ys + ((size_t)(b * 128 + h) * 8 + kcg) * 8192;
                if (w > 0) {
                    *(__half*)(ysb + ysoff(kk_a, w - 1)) = __low2half(uh);
                    *(__half*)(ysb + ysoff(kk_b, w - 1)) = __low2half(vh);
                }
                *(__half*)(ysb + ysoff(kk_a, w)) = __high2half(uh);
                *(__half*)(ysb + ysoff(kk_b, w)) = __high2half(vh);
            }
        }
    }
}

// --------------------------- conv1x1(shifted y) + bias + BN + id + SiLU ----
__global__ __launch_bounds__(NTHR, 2) void k_pw(
    const float* __restrict__ b1,
    const float* __restrict__ gamma, const float* __restrict__ beta,
    const float* __restrict__ mean,  const float* __restrict__ var,
    float* __restrict__ out)
{
    extern __shared__ __align__(16) char dsm[];
    __shared__ __align__(8) unsigned long long s_mb[NSTG];
    const uint smb = smem_u32(dsm);
    const uint mbb = smem_u32(&s_mb[0]);

    const int tid = threadIdx.x;
    const int wrp = tid >> 5, lane = tid & 31;
    const int wm = wrp >> 1, wn = wrp & 1;
    const int h0  = blockIdx.x;
    const int ocg = blockIdx.y, oc0 = ocg * 128;
    const int b   = blockIdx.z;

    if (tid < NSTG) MBAR_INIT(mbb + tid * 8, 1);
    __syncthreads();

    float acc[2][8][4];
#pragma unroll
    for (int i = 0; i < 2; ++i)
#pragma unroll
        for (int jj = 0; jj < 8; ++jj)
#pragma unroll
            for (int q = 0; q < 4; ++q) acc[i][jj][q] = 0.0f;

#define ISSUE_PW(nit, s) do { \
        uint mbx = mbb + (s) * 8; \
        MBAR_EXPECT(mbx, 16384u); \
        BULK_G2S(smb + (s) * STAGE, \
                 (const char*)g_wB16 + (size_t)((nit) * 2 + ocg) * 8192, 8192u, mbx); \
        size_t blk_ = ((size_t)(b * 128 + h0) * 8 + (nit)); \
        BULK_G2S(smb + (s) * STAGE + A_BYTES, \
                 (const char*)g_ys + blk_ * 8192, 8192u, mbx); \
    } while (0)

    if (tid == 0) { ISSUE_PW(0, 0); ISSUE_PW(1, 1); ISSUE_PW(2, 2); }

#pragma unroll 1
    for (int it = 0; it < 8; ++it) {
        mbar_wait(mbb + (it & 3) * 8, (uint)((it >> 2) & 1));
        const uint sb = smb + (it & 3) * STAGE;
        mma_chunk(sb, sb + A_BYTES, wm, wn, lane, acc);
        __syncthreads();
        if (tid == 0 && it + 3 < 8) ISSUE_PW(it + 3, (it + 3) & 3);
    }
#undef ISSUE_PW

    // epilogue: +bias, BN, +identity(fp16), SiLU -> out (fp32)
    const int h = h0;
#pragma unroll
    for (int mf = 0; mf < 2; ++mf) {
        const int oc_a = oc0 + wm * 32 + mf * 16 + (lane >> 2);
        const int oc_b = oc_a + 8;
        const float inva = __ldg(&gamma[oc_a]) * rsqrtf(__ldg(&var[oc_a]) + EPSBN);
        const float bba  = __ldg(&beta[oc_a]) - __ldg(&mean[oc_a]) * inva;
        const float bsa  = __ldg(&b1[oc_a]);
        const float invb = __ldg(&gamma[oc_b]) * rsqrtf(__ldg(&var[oc_b]) + EPSBN);
        const float bbb  = __ldg(&beta[oc_b]) - __ldg(&mean[oc_b]) * invb;
        const float bsb  = __ldg(&b1[oc_b]);
        const size_t ra = ((size_t)b * C2 + oc_a) * HW;
        const size_t rb = ((size_t)b * C2 + oc_b) * HW;
#pragma unroll
        for (int nf = 0; nf < 8; ++nf) {
            const int w = wn * 64 + nf * 8 + (lane & 3) * 2;
            const int off = h * W_ + w;
            float2 ida = __half22float2(*(const __half2*)(g_yi + ra + off));
            float2 idb = __half22float2(*(const __half2*)(g_yi + rb + off));
            float2 u, v; float z;
            z = (acc[mf][nf][0] + bsa) * inva + bba + ida.x; u.x = silu_f(z);
            z = (acc[mf][nf][1] + bsa) * inva + bba + ida.y; u.y = silu_f(z);
            z = (acc[mf][nf][2] + bsb) * invb + bbb + idb.x; v.x = silu_f(z);
            z = (acc[mf][nf][3] + bsb) * invb + bbb + idb.y; v.y = silu_f(z);
            *(float2*)(out + ra + off) = u;
            *(float2*)(out + rb + off) = v;
        }
    }
}

// ---------------------------------------------------------------------------
extern "C" void kernel_launch(void* const* d_in, const int* in_sizes, int n_in,
                              void* d_out, int out_size)
{
    const float* x     = (const float*)d_in[0];
    const float* wconv = (const float*)d_in[1];
    const float* w1    = (const float*)d_in[2];
    const float* b1    = (const float*)d_in[3];
    const float* gamma = (const float*)d_in[4];
    const float* beta  = (const float*)d_in[5];
    const float* mean  = (const float*)d_in[6];
    const float* var   = (const float*)d_in[7];
    float* out = (float*)d_out;

    static bool attr_done = false;
    if (!attr_done) {
        cudaFuncSetAttribute(k_conv3, cudaFuncAttributeMaxDynamicSharedMemorySize, DSMEM_BYTES);
        cudaFuncSetAttribute(k_pw,    cudaFuncAttributeMaxDynamicSharedMemorySize, DSMEM_BYTES);
        attr_done = true;
    }

    k_repack_conv<<<(C2 * C1 * 9 + 255) / 256, 256>>>(wconv);
    k_repack_pw  <<<(C2 * C2 + 255) / 256, 256>>>(w1);
    k_prep_x     <<<dim3(H_, B_), 256>>>(x);
    k_zero_xs    <<<384, 256>>>();
    k_zero_ys    <<<262144 / 256, 256>>>();
    k_zero_ys_blk<<<64, 256>>>();

    dim3 grid(H_, 2, B_);   // 128 rows x 2 ocg x 16 batch = 4096 CTAs
    k_conv3<<<grid, NTHR, DSMEM_BYTES>>>(gamma, beta, mean, var);
    k_pw   <<<grid, NTHR, DSMEM_BYTES>>>(b1, gamma, beta, mean, var, out);
}

// round 14
// speedup vs baseline: 1.2590x; 1.0675x over previous
#include <cuda_runtime.h>
#include <cuda_fp16.h>

// SConv R13: R12 bulk-staged GEMMs with full/empty mbarrier pipeline
// (no per-chunk __syncthreads; warps skew freely). NSTG=5, prefetch 4.
// CTA: 256 thr (8 warps 4Mx2N, warp 32x64), tile 128oc x 128px, 2 CTAs/SM.

#define B_  16
#define C1  128
#define C2  256
#define H_  128
#define W_  128
#define HW  (H_*W_)
#define EPSBN 1e-5f

typedef unsigned int uint;

// x tiles: [kx 3][b 16][hp 130][kc 4] blocks of 8KB (32ch x 128w fp16, swizzled)
__device__ __half g_xs[(size_t)3 * B_ * 130 * 4 * 4096];
// y shifted tiles (pw B operand): [b][h 128][kc 8] blocks of 8KB, swizzled
__device__ __half g_ys[(size_t)B_ * 128 * 8 * 4096];
__device__ __half g_yi [(size_t)B_ * C2 * HW];    // y fp16 plain (identity)
__device__ __half g_wA16[36 * 2 * 4096];          // conv w, frag order
__device__ __half g_wB16[ 8 * 2 * 4096];          // 1x1 w, frag order

__device__ __forceinline__ float silu_f(float v) { return v / (1.0f + __expf(-v)); }
__device__ __forceinline__ uint smem_u32(const void* p) {
    uint a;
    asm("{ .reg .u64 t; cvta.to.shared.u64 t, %1; cvt.u32.u64 %0, t; }" : "=r"(a) : "l"(p));
    return a;
}

#define MMA16(d, a, b0v, b1v) \
    asm volatile("mma.sync.aligned.m16n8k16.row.col.f32.f16.f16.f32 " \
        "{%0,%1,%2,%3}, {%4,%5,%6,%7}, {%8,%9}, {%0,%1,%2,%3};" \
        : "+f"((d)[0]), "+f"((d)[1]), "+f"((d)[2]), "+f"((d)[3]) \
        : "r"((a).x), "r"((a).y), "r"((a).z), "r"((a).w), "r"(b0v), "r"(b1v))

#define MBAR_INIT(a, c) \
    asm volatile("mbarrier.init.shared.b64 [%0], %1;" :: "r"(a), "r"(c) : "memory")
#define MBAR_EXPECT(a, by) \
    asm volatile("mbarrier.arrive.expect_tx.shared.b64 _, [%0], %1;" :: "r"(a), "r"(by) : "memory")
#define MBAR_ARRIVE(a) \
    asm volatile("mbarrier.arrive.shared.b64 _, [%0];" :: "r"(a) : "memory")
#define BULK_G2S(dst, src, sz, mb) \
    asm volatile("cp.async.bulk.shared::cta.global.mbarrier::complete_tx::bytes [%0], [%1], %2, [%3];" \
        :: "r"(dst), "l"(src), "r"(sz), "r"(mb) : "memory")
__device__ __forceinline__ void mbar_wait(uint a, uint ph) {
    asm volatile(
        "{\n\t.reg .pred P;\n\tWL%=:\n\t"
        "mbarrier.try_wait.parity.shared.b64 P, [%0], %1;\n\t"
        "@!P bra WL%=;\n\t}" :: "r"(a), "r"(ph) : "memory");
}

// Chunk (K=32): A 8192 B (128oc frag order) + B 8192 B ([kk 32][n 128],
// 256B rows, 16B-granule XOR swizzle: granule (kk,g) at kk*256 + ((g^(kk&7))<<4)).
#define A_BYTES 8192
#define B_BYTES 8192
#define STAGE   (A_BYTES + B_BYTES)   // 16384
#define NSTG    5
#define PREF    4
#define DSMEM_BYTES (NSTG * STAGE)    // 81920 per CTA, 2 CTAs/SM

#define NTHR 256

// swizzled byte offset of (kk, w) inside an 8KB B tile
__device__ __forceinline__ int ysoff(int kk, int wp) {
    return kk * 256 + ((((wp >> 3) ^ (kk & 7))) << 4) + (wp & 7) * 2;
}

// --------------------------------------------------------- prep kernels ----
__device__ __forceinline__ int fragoff(int m, int kk) {
    return (((kk >> 4) * 8 + (m >> 4)) * 32 + (((m & 7) << 2) | ((kk >> 1) & 3))) * 8
         + (((kk >> 3) & 1) * 2 + ((m >> 3) & 1)) * 2 + (kk & 1);
}
// merged weight repack (conv then pw ranges)
__global__ __launch_bounds__(256) void k_repack(const float* __restrict__ wc,
                                                const float* __restrict__ w1) {
    int idx = blockIdx.x * 256 + threadIdx.x;
    if (idx < C2 * C1 * 9) {
        int tap = idx % 9, rest = idx / 9;
        int ic = rest % C1, oc = rest / C1;
        int it = (ic >> 5) * 9 + tap;
        g_wA16[(size_t)(it * 2 + (oc >> 7)) * 4096 + fragoff(oc & 127, ic & 31)] =
            __float2half_rn(wc[idx]);
    } else {
        int j = idx - C2 * C1 * 9;
        if (j >= C2 * C2) return;
        int ic = j % C2, oc = j / C2;
        g_wB16[(size_t)((ic >> 5) * 2 + (oc >> 7)) * 4096 + fragoff(oc & 127, ic & 31)] =
            __float2half_rn(w1[j]);
    }
}

// x fp32 -> 3 column-shift variants, swizzled 8KB tiles, halo rows at hp 0/129
__global__ __launch_bounds__(256) void k_prep_x(const float* __restrict__ x) {
    const int h = blockIdx.x, b = blockIdx.y;
    const int tid = threadIdx.x;
#pragma unroll
    for (int i = 0; i < 8; ++i) {
        int item = tid + i * 256;            // 0..2047
        int kc = item >> 9, r = item & 511;
        int kk = r >> 4, g = r & 15;
        const float* src = x + (((size_t)(b * C1 + kc * 32 + kk)) * H_ + h) * W_;
        int w0 = g * 8;
        float v[10];
#pragma unroll
        for (int j = 0; j < 10; ++j) {
            int gw = w0 - 1 + j;
            v[j] = ((uint)gw < 128u) ? __ldg(src + gw) : 0.f;
        }
        uint off = (uint)(kk * 256 + ((g ^ (kk & 7)) << 4));
#pragma unroll
        for (int kx = 0; kx < 3; ++kx) {
            __align__(16) __half hh[8];
#pragma unroll
            for (int j = 0; j < 8; ++j) hh[j] = __float2half_rn(v[j + kx]);
            size_t blk = ((size_t)(kx * B_ + b) * 130 + (h + 1)) * 4 + kc;
            *(uint4*)((char*)g_xs + blk * 8192 + off) = *(const uint4*)hh;
        }
    }
}

// merged zero kernel: xs halo rows + ys border blocks + ys border columns
#define Z_S0 196608                      // 384 blks x 512 uint4 (xs halo)
#define Z_S1 32768                       // 64 blks x 512 uint4 (ys blocks)
#define Z_S2 262144                      // ys border halfs
__global__ __launch_bounds__(256) void k_zero() {
    int idx = blockIdx.x * 256 + threadIdx.x;
    if (idx < Z_S0) {
        int i512 = idx >> 9, j = idx & 511;
        int kx = i512 % 3, rest = i512 / 3;
        int b = rest % 16; rest /= 16;
        int e = rest % 2, kc = rest / 2;
        size_t blk = ((size_t)(kx * B_ + b) * 130 + (e ? 129 : 0)) * 4 + kc;
        ((uint4*)((char*)g_xs + blk * 8192))[j] = make_uint4(0, 0, 0, 0);
    } else if (idx < Z_S0 + Z_S1) {
        int i = idx - Z_S0;
        int i512 = i >> 9, j = i & 511;
        int b = i512 >> 2, q = i512 & 3;
        int kc = (q < 2) ? 2 + q : 6 + (q - 2);
        int hh = (q < 2) ? 127 : 0;
        size_t blk = ((size_t)(b * 128 + hh) * 8 + kc);
        ((uint4*)((char*)g_ys + blk * 8192))[j] = make_uint4(0, 0, 0, 0);
    } else {
        int i = idx - Z_S0 - Z_S1;
        if (i >= Z_S2) return;
        int sel = i >> 17, r = i & 131071;
        int b = r >> 13, r2 = r & 8191;
        int hh = r2 >> 6, r3 = r2 & 63;
        int kc2 = r3 >> 5, kk = r3 & 31;
        int kc, wp;
        if (sel == 0) { kc = kc2;     wp = 0;   }
        else          { kc = 4 + kc2; wp = 127; }
        size_t blk = ((size_t)(b * 128 + hh) * 8 + kc);
        *(__half*)((char*)g_ys + blk * 8192 + ysoff(kk, wp)) = __float2half_rn(0.f);
    }
}

// ----------------------------------------------------------------- MMA -----
// warp tile 32oc x 64px: wm=wrp>>1 (0..3), wn=wrp&1. mf 0..1, nf 0..7.
__device__ __forceinline__ void mma_chunk(uint Asm, uint Bsm, int wm, int wn,
                                          int lane, float acc[2][8][4]) {
    const int j = lane >> 3, r = lane & 7;
    const int jk = (j & 1) << 3, jn = j >> 1;
#pragma unroll
    for (int ks = 0; ks < 2; ++ks) {
        uint4 a[2];
#pragma unroll
        for (int mf = 0; mf < 2; ++mf) {
            uint ad = Asm + (((ks * 8 + wm * 2 + mf) * 32 + lane) << 4);
            asm volatile("ld.shared.v4.b32 {%0,%1,%2,%3}, [%4];"
                : "=r"(a[mf].x), "=r"(a[mf].y), "=r"(a[mf].z), "=r"(a[mf].w) : "r"(ad));
        }
        uint bf[8][2];
#pragma unroll
        for (int p = 0; p < 4; ++p) {
            int krow = ks * 16 + jk + r;
            int oct  = wn * 8 + 2 * p + jn;
            uint ad = Bsm + krow * 256 + ((uint)(oct ^ (krow & 7)) << 4);
            uint d0, d1, d2, d3;
            asm volatile("ldmatrix.sync.aligned.m8n8.x4.trans.shared.b16 "
                "{%0,%1,%2,%3}, [%4];"
                : "=r"(d0), "=r"(d1), "=r"(d2), "=r"(d3) : "r"(ad));
            bf[2 * p][0] = d0; bf[2 * p][1] = d1;
            bf[2 * p + 1][0] = d2; bf[2 * p + 1][1] = d3;
        }
#pragma unroll
        for (int mf = 0; mf < 2; ++mf)
#pragma unroll
            for (int nf = 0; nf < 8; ++nf)
                MMA16(acc[mf][nf], a[mf], bf[nf][0], bf[nf][1]);
    }
}

// ------------------------------------------------------ conv3x3 + BN + SiLU
__global__ __launch_bounds__(NTHR, 2) void k_conv3(
    const float* __restrict__ gamma, const float* __restrict__ beta,
    const float* __restrict__ mean,  const float* __restrict__ var)
{
    extern __shared__ __align__(16) char dsm[];
    __shared__ __align__(8) unsigned long long s_full[NSTG], s_empty[NSTG];
    const uint smb = smem_u32(dsm);
    const uint fullb = smem_u32(&s_full[0]);
    const uint emptyb = smem_u32(&s_empty[0]);

    const int tid = threadIdx.x;
    const int wrp = tid >> 5, lane = tid & 31;
    const int wm = wrp >> 1, wn = wrp & 1;
    const int h0  = blockIdx.x;
    const int ocg = blockIdx.y, oc0 = ocg * 128;
    const int b   = blockIdx.z;

    if (tid < NSTG) { MBAR_INIT(fullb + tid * 8, 1); MBAR_INIT(emptyb + tid * 8, 8); }
    __syncthreads();

    float acc[2][8][4];
#pragma unroll
    for (int i = 0; i < 2; ++i)
#pragma unroll
        for (int jj = 0; jj < 8; ++jj)
#pragma unroll
            for (int q = 0; q < 4; ++q) acc[i][jj][q] = 0.0f;

#define ISSUE_CONV(nit, s) do { \
        int kc_ = (nit) / 9, tap_ = (nit) - 9 * kc_; \
        int ky_ = tap_ / 3, kx_ = tap_ - 3 * ky_; \
        uint mbx = fullb + (s) * 8; \
        MBAR_EXPECT(mbx, 16384u); \
        BULK_G2S(smb + (s) * STAGE, \
                 (const char*)g_wA16 + (size_t)((nit) * 2 + ocg) * 8192, 8192u, mbx); \
        size_t blk_ = ((size_t)(kx_ * B_ + b) * 130 + (h0 + ky_)) * 4 + kc_; \
        BULK_G2S(smb + (s) * STAGE + A_BYTES, \
                 (const char*)g_xs + blk_ * 8192, 8192u, mbx); \
    } while (0)

    if (tid == 0) {
        ISSUE_CONV(0, 0); ISSUE_CONV(1, 1); ISSUE_CONV(2, 2); ISSUE_CONV(3, 3);
    }

#pragma unroll 1
    for (int it = 0; it < 36; ++it) {
        const int s = it % NSTG;
        mbar_wait(fullb + s * 8, (uint)((it / NSTG) & 1));
        const uint sb = smb + s * STAGE;
        mma_chunk(sb, sb + A_BYTES, wm, wn, lane, acc);
        if (lane == 0) MBAR_ARRIVE(emptyb + s * 8);
        const int nx = it + PREF;
        if (nx < 36 && tid == 0) {
            const int sn = nx % NSTG, un = nx / NSTG;
            if (un >= 1) mbar_wait(emptyb + sn * 8, (uint)((un - 1) & 1));
            ISSUE_CONV(nx, sn);
        }
    }
#undef ISSUE_CONV

    // epilogue: BN + SiLU -> g_yi (linear) + g_ys (shifted, swizzled tiles)
    const int kcg = (oc0 >> 5) + wm;          // global kc of this warp's 32 oc
    const int grp = (kcg >> 1) & 3;
    const int h = h0;
#pragma unroll
    for (int mf = 0; mf < 2; ++mf) {
        const int kk_a = mf * 16 + (lane >> 2), kk_b = kk_a + 8;
        const int oc_a = kcg * 32 + kk_a, oc_b = oc_a + 8;
        const float inva = __ldg(&gamma[oc_a]) * rsqrtf(__ldg(&var[oc_a]) + EPSBN);
        const float bba  = __ldg(&beta[oc_a]) - __ldg(&mean[oc_a]) * inva;
        const float invb = __ldg(&gamma[oc_b]) * rsqrtf(__ldg(&var[oc_b]) + EPSBN);
        const float bbb  = __ldg(&beta[oc_b]) - __ldg(&mean[oc_b]) * invb;
        const size_t ra = ((size_t)b * C2 + oc_a) * HW;
        const size_t rb = ((size_t)b * C2 + oc_b) * HW;
#pragma unroll
        for (int nf = 0; nf < 8; ++nf) {
            const int w = wn * 64 + nf * 8 + (lane & 3) * 2;
            const int off = h * W_ + w;
            float2 u, v;
            u.x = silu_f(acc[mf][nf][0] * inva + bba);
            u.y = silu_f(acc[mf][nf][1] * inva + bba);
            v.x = silu_f(acc[mf][nf][2] * invb + bbb);
            v.y = silu_f(acc[mf][nf][3] * invb + bbb);
            __half2 uh = __floats2half2_rn(u.x, u.y);
            __half2 vh = __floats2half2_rn(v.x, v.y);
            *(__half2*)(g_yi + ra + off) = uh;
            *(__half2*)(g_yi + rb + off) = vh;
            if (grp == 1) {                   // dest (h-1, w)
                if (h > 0) {
                    char* ysb = (char*)g_ys + ((size_t)(b * 128 + h - 1) * 8 + kcg) * 8192;
                    *(__half2*)(ysb + ysoff(kk_a, w)) = uh;
                    *(__half2*)(ysb + ysoff(kk_b, w)) = vh;
                }
            } else if (grp == 3) {            // dest (h+1, w)
                if (h < 127) {
                    char* ysb = (char*)g_ys + ((size_t)(b * 128 + h + 1) * 8 + kcg) * 8192;
                    *(__half2*)(ysb + ysoff(kk_a, w)) = uh;
                    *(__half2*)(ysb + ysoff(kk_b, w)) = vh;
                }
            } else if (grp == 0) {            // dest (h, w+1)
                char* ysb = (char*)g_ys + ((size_t)(b * 128 + h) * 8 + kcg) * 8192;
                *(__half*)(ysb + ysoff(kk_a, w + 1)) = __low2half(uh);
                *(__half*)(ysb + ysoff(kk_b, w + 1)) = __low2half(vh);
                if (w < 126) {
                    *(__half*)(ysb + ysoff(kk_a, w + 2)) = __high2half(uh);
                    *(__half*)(ysb + ysoff(kk_b, w + 2)) = __high2half(vh);
                }
            } else {                          // grp 2: dest (h, w-1)
                char* ysb = (char*)g_ys + ((size_t)(b * 128 + h) * 8 + kcg) * 8192;
                if (w > 0) {
                    *(__half*)(ysb + ysoff(kk_a, w - 1)) = __low2half(uh);
                    *(__half*)(ysb + ysoff(kk_b, w - 1)) = __low2half(vh);
                }
                *(__half*)(ysb + ysoff(kk_a, w)) = __high2half(uh);
                *(__half*)(ysb + ysoff(kk_b, w)) = __high2half(vh);
            }
        }
    }
}

// --------------------------- conv1x1(shifted y) + bias + BN + id + SiLU ----
__global__ __launch_bounds__(NTHR, 2) void k_pw(
    const float* __restrict__ b1,
    const float* __restrict__ gamma, const float* __restrict__ beta,
    const float* __restrict__ mean,  const float* __restrict__ var,
    float* __restrict__ out)
{
    extern __shared__ __align__(16) char dsm[];
    __shared__ __align__(8) unsigned long long s_full[NSTG], s_empty[NSTG];
    const uint smb = smem_u32(dsm);
    const uint fullb = smem_u32(&s_full[0]);
    const uint emptyb = smem_u32(&s_empty[0]);

    const int tid = threadIdx.x;
    const int wrp = tid >> 5, lane = tid & 31;
    const int wm = wrp >> 1, wn = wrp & 1;
    const int h0  = blockIdx.x;
    const int ocg = blockIdx.y, oc0 = ocg * 128;
    const int b   = blockIdx.z;

    if (tid < NSTG) { MBAR_INIT(fullb + tid * 8, 1); MBAR_INIT(emptyb + tid * 8, 8); }
    __syncthreads();

    float acc[2][8][4];
#pragma unroll
    for (int i = 0; i < 2; ++i)
#pragma unroll
        for (int jj = 0; jj < 8; ++jj)
#pragma unroll
            for (int q = 0; q < 4; ++q) acc[i][jj][q] = 0.0f;

#define ISSUE_PW(nit, s) do { \
        uint mbx = fullb + (s) * 8; \
        MBAR_EXPECT(mbx, 16384u); \
        BULK_G2S(smb + (s) * STAGE, \
                 (const char*)g_wB16 + (size_t)((nit) * 2 + ocg) * 8192, 8192u, mbx); \
        size_t blk_ = ((size_t)(b * 128 + h0) * 8 + (nit)); \
        BULK_G2S(smb + (s) * STAGE + A_BYTES, \
                 (const char*)g_ys + blk_ * 8192, 8192u, mbx); \
    } while (0)

    if (tid == 0) {
        ISSUE_PW(0, 0); ISSUE_PW(1, 1); ISSUE_PW(2, 2); ISSUE_PW(3, 3);
    }

#pragma unroll 1
    for (int it = 0; it < 8; ++it) {
        const int s = it % NSTG;
        mbar_wait(fullb + s * 8, (uint)((it / NSTG) & 1));
        const uint sb = smb + s * STAGE;
        mma_chunk(sb, sb + A_BYTES, wm, wn, lane, acc);
        if (lane == 0) MBAR_ARRIVE(emptyb + s * 8);
        const int nx = it + PREF;
        if (nx < 8 && tid == 0) {
            const int sn = nx % NSTG, un = nx / NSTG;
            if (un >= 1) mbar_wait(emptyb + sn * 8, (uint)((un - 1) & 1));
            ISSUE_PW(nx, sn);
        }
    }
#undef ISSUE_PW

    // epilogue: +bias, BN, +identity(fp16), SiLU -> out (fp32)
    const int h = h0;
#pragma unroll
    for (int mf = 0; mf < 2; ++mf) {
        const int oc_a = oc0 + wm * 32 + mf * 16 + (lane >> 2);
        const int oc_b = oc_a + 8;
        const float inva = __ldg(&gamma[oc_a]) * rsqrtf(__ldg(&var[oc_a]) + EPSBN);
        const float bba  = __ldg(&beta[oc_a]) - __ldg(&mean[oc_a]) * inva;
        const float bsa  = __ldg(&b1[oc_a]);
        const float invb = __ldg(&gamma[oc_b]) * rsqrtf(__ldg(&var[oc_b]) + EPSBN);
        const float bbb  = __ldg(&beta[oc_b]) - __ldg(&mean[oc_b]) * invb;
        const float bsb  = __ldg(&b1[oc_b]);
        const size_t ra = ((size_t)b * C2 + oc_a) * HW;
        const size_t rb = ((size_t)b * C2 + oc_b) * HW;
#pragma unroll
        for (int nf = 0; nf < 8; ++nf) {
            const int w = wn * 64 + nf * 8 + (lane & 3) * 2;
            const int off = h * W_ + w;
            float2 ida = __half22float2(*(const __half2*)(g_yi + ra + off));
            float2 idb = __half22float2(*(const __half2*)(g_yi + rb + off));
            float2 u, v; float z;
            z = (acc[mf][nf][0] + bsa) * inva + bba + ida.x; u.x = silu_f(z);
            z = (acc[mf][nf][1] + bsa) * inva + bba + ida.y; u.y = silu_f(z);
            z = (acc[mf][nf][2] + bsb) * invb + bbb + idb.x; v.x = silu_f(z);
            z = (acc[mf][nf][3] + bsb) * invb + bbb + idb.y; v.y = silu_f(z);
            *(float2*)(out + ra + off) = u;
            *(float2*)(out + rb + off) = v;
        }
    }
}

// ---------------------------------------------------------------------------
extern "C" void kernel_launch(void* const* d_in, const int* in_sizes, int n_in,
                              void* d_out, int out_size)
{
    const float* x     = (const float*)d_in[0];
    const float* wconv = (const float*)d_in[1];
    const float* w1    = (const float*)d_in[2];
    const float* b1    = (const float*)d_in[3];
    const float* gamma = (const float*)d_in[4];
    const float* beta  = (const float*)d_in[5];
    const float* mean  = (const float*)d_in[6];
    const float* var   = (const float*)d_in[7];
    float* out = (float*)d_out;

    static bool attr_done = false;
    if (!attr_done) {
        cudaFuncSetAttribute(k_conv3, cudaFuncAttributeMaxDynamicSharedMemorySize, DSMEM_BYTES);
        cudaFuncSetAttribute(k_pw,    cudaFuncAttributeMaxDynamicSharedMemorySize, DSMEM_BYTES);
        attr_done = true;
    }

    k_repack<<<(C2 * C1 * 9 + C2 * C2 + 255) / 256, 256>>>(wconv, w1);
    k_prep_x<<<dim3(H_, B_), 256>>>(x);
    k_zero  <<<(Z_S0 + Z_S1 + Z_S2 + 255) / 256, 256>>>();

    dim3 grid(H_, 2, B_);   // 128 rows x 2 ocg x 16 batch = 4096 CTAs
    k_conv3<<<grid, NTHR, DSMEM_BYTES>>>(gamma, beta, mean, var);
    k_pw   <<<grid, NTHR, DSMEM_BYTES>>>(b1, gamma, beta, mean, var, out);
}

// round 15
// speedup vs baseline: 1.3415x; 1.0655x over previous
#include <cuda_runtime.h>
#include <cuda_fp16.h>

// SConv R14: R13 with constant-folded pipeline. NSTG=4, main loops unrolled x4
// (stage offsets & mbar addrs compile-time), fragment addresses hoisted.
// CTA: 256 thr (8 warps 4Mx2N, warp 32x64), tile 128oc x 128px, 2 CTAs/SM.

#define B_  16
#define C1  128
#define C2  256
#define H_  128
#define W_  128
#define HW  (H_*W_)
#define EPSBN 1e-5f

typedef unsigned int uint;

// x tiles: [kx 3][b 16][hp 130][kc 4] blocks of 8KB (32ch x 128w fp16, swizzled)
__device__ __half g_xs[(size_t)3 * B_ * 130 * 4 * 4096];
// y shifted tiles (pw B operand): [b][h 128][kc 8] blocks of 8KB, swizzled
__device__ __half g_ys[(size_t)B_ * 128 * 8 * 4096];
__device__ __half g_yi [(size_t)B_ * C2 * HW];    // y fp16 plain (identity)
__device__ __half g_wA16[36 * 2 * 4096];          // conv w, frag order
__device__ __half g_wB16[ 8 * 2 * 4096];          // 1x1 w, frag order

__device__ __forceinline__ float silu_f(float v) { return v / (1.0f + __expf(-v)); }
__device__ __forceinline__ uint smem_u32(const void* p) {
    uint a;
    asm("{ .reg .u64 t; cvta.to.shared.u64 t, %1; cvt.u32.u64 %0, t; }" : "=r"(a) : "l"(p));
    return a;
}

#define MMA16(d, a, b0v, b1v) \
    asm volatile("mma.sync.aligned.m16n8k16.row.col.f32.f16.f16.f32 " \
        "{%0,%1,%2,%3}, {%4,%5,%6,%7}, {%8,%9}, {%0,%1,%2,%3};" \
        : "+f"((d)[0]), "+f"((d)[1]), "+f"((d)[2]), "+f"((d)[3]) \
        : "r"((a).x), "r"((a).y), "r"((a).z), "r"((a).w), "r"(b0v), "r"(b1v))

#define MBAR_INIT(a, c) \
    asm volatile("mbarrier.init.shared.b64 [%0], %1;" :: "r"(a), "r"(c) : "memory")
#define MBAR_EXPECT(a, by) \
    asm volatile("mbarrier.arrive.expect_tx.shared.b64 _, [%0], %1;" :: "r"(a), "r"(by) : "memory")
#define MBAR_ARRIVE(a) \
    asm volatile("mbarrier.arrive.shared.b64 _, [%0];" :: "r"(a) : "memory")
#define BULK_G2S(dst, src, sz, mb) \
    asm volatile("cp.async.bulk.shared::cta.global.mbarrier::complete_tx::bytes [%0], [%1], %2, [%3];" \
        :: "r"(dst), "l"(src), "r"(sz), "r"(mb) : "memory")
__device__ __forceinline__ void mbar_wait(uint a, uint ph) {
    asm volatile(
        "{\n\t.reg .pred P;\n\tWL%=:\n\t"
        "mbarrier.try_wait.parity.shared.b64 P, [%0], %1;\n\t"
        "@!P bra WL%=;\n\t}" :: "r"(a), "r"(ph) : "memory");
}

// Chunk (K=32): A 8192 B (128oc frag order) + B 8192 B ([kk 32][n 128],
// 256B rows, 16B-granule XOR swizzle: granule (kk,g) at kk*256 + ((g^(kk&7))<<4)).
#define A_BYTES 8192
#define B_BYTES 8192
#define STAGE   (A_BYTES + B_BYTES)   // 16384
#define NSTG    4
#define DSMEM_BYTES (NSTG * STAGE)    // 65536 per CTA, 2 CTAs/SM

#define NTHR 256

// swizzled byte offset of (kk, w) inside an 8KB B tile
__device__ __forceinline__ int ysoff(int kk, int wp) {
    return kk * 256 + ((((wp >> 3) ^ (kk & 7))) << 4) + (wp & 7) * 2;
}

// --------------------------------------------------------- prep kernels ----
__device__ __forceinline__ int fragoff(int m, int kk) {
    return (((kk >> 4) * 8 + (m >> 4)) * 32 + (((m & 7) << 2) | ((kk >> 1) & 3))) * 8
         + (((kk >> 3) & 1) * 2 + ((m >> 3) & 1)) * 2 + (kk & 1);
}
__global__ __launch_bounds__(256) void k_repack(const float* __restrict__ wc,
                                                const float* __restrict__ w1) {
    int idx = blockIdx.x * 256 + threadIdx.x;
    if (idx < C2 * C1 * 9) {
        int tap = idx % 9, rest = idx / 9;
        int ic = rest % C1, oc = rest / C1;
        int it = (ic >> 5) * 9 + tap;
        g_wA16[(size_t)(it * 2 + (oc >> 7)) * 4096 + fragoff(oc & 127, ic & 31)] =
            __float2half_rn(wc[idx]);
    } else {
        int j = idx - C2 * C1 * 9;
        if (j >= C2 * C2) return;
        int ic = j % C2, oc = j / C2;
        g_wB16[(size_t)((ic >> 5) * 2 + (oc >> 7)) * 4096 + fragoff(oc & 127, ic & 31)] =
            __float2half_rn(w1[j]);
    }
}

__global__ __launch_bounds__(256) void k_prep_x(const float* __restrict__ x) {
    const int h = blockIdx.x, b = blockIdx.y;
    const int tid = threadIdx.x;
#pragma unroll
    for (int i = 0; i < 8; ++i) {
        int item = tid + i * 256;            // 0..2047
        int kc = item >> 9, r = item & 511;
        int kk = r >> 4, g = r & 15;
        const float* src = x + (((size_t)(b * C1 + kc * 32 + kk)) * H_ + h) * W_;
        int w0 = g * 8;
        float v[10];
#pragma unroll
        for (int j = 0; j < 10; ++j) {
            int gw = w0 - 1 + j;
            v[j] = ((uint)gw < 128u) ? __ldg(src + gw) : 0.f;
        }
        uint off = (uint)(kk * 256 + ((g ^ (kk & 7)) << 4));
#pragma unroll
        for (int kx = 0; kx < 3; ++kx) {
            __align__(16) __half hh[8];
#pragma unroll
            for (int j = 0; j < 8; ++j) hh[j] = __float2half_rn(v[j + kx]);
            size_t blk = ((size_t)(kx * B_ + b) * 130 + (h + 1)) * 4 + kc;
            *(uint4*)((char*)g_xs + blk * 8192 + off) = *(const uint4*)hh;
        }
    }
}

#define Z_S0 196608
#define Z_S1 32768
#define Z_S2 262144
__global__ __launch_bounds__(256) void k_zero() {
    int idx = blockIdx.x * 256 + threadIdx.x;
    if (idx < Z_S0) {
        int i512 = idx >> 9, j = idx & 511;
        int kx = i512 % 3, rest = i512 / 3;
        int b = rest % 16; rest /= 16;
        int e = rest % 2, kc = rest / 2;
        size_t blk = ((size_t)(kx * B_ + b) * 130 + (e ? 129 : 0)) * 4 + kc;
        ((uint4*)((char*)g_xs + blk * 8192))[j] = make_uint4(0, 0, 0, 0);
    } else if (idx < Z_S0 + Z_S1) {
        int i = idx - Z_S0;
        int i512 = i >> 9, j = i & 511;
        int b = i512 >> 2, q = i512 & 3;
        int kc = (q < 2) ? 2 + q : 6 + (q - 2);
        int hh = (q < 2) ? 127 : 0;
        size_t blk = ((size_t)(b * 128 + hh) * 8 + kc);
        ((uint4*)((char*)g_ys + blk * 8192))[j] = make_uint4(0, 0, 0, 0);
    } else {
        int i = idx - Z_S0 - Z_S1;
        if (i >= Z_S2) return;
        int sel = i >> 17, r = i & 131071;
        int b = r >> 13, r2 = r & 8191;
        int hh = r2 >> 6, r3 = r2 & 63;
        int kc2 = r3 >> 5, kk = r3 & 31;
        int kc, wp;
        if (sel == 0) { kc = kc2;     wp = 0;   }
        else          { kc = 4 + kc2; wp = 127; }
        size_t blk = ((size_t)(b * 128 + hh) * 8 + kc);
        *(__half*)((char*)g_ys + blk * 8192 + ysoff(kk, wp)) = __float2half_rn(0.f);
    }
}

// ----------------------------------------------------------------- MMA -----
// Hoisted per-thread fragment addresses (stage-0 based).
struct FragAddr { uint a[4]; uint b[8]; };

__device__ __forceinline__ void frag_init(FragAddr& fa, uint smb, int wm, int wn,
                                          int lane) {
    const int j = lane >> 3, r = lane & 7;
    const int jk = (j & 1) << 3, jn = j >> 1;
#pragma unroll
    for (int ks = 0; ks < 2; ++ks) {
#pragma unroll
        for (int mf = 0; mf < 2; ++mf)
            fa.a[ks * 2 + mf] = smb + (((ks * 8 + wm * 2 + mf) * 32 + lane) << 4);
#pragma unroll
        for (int p = 0; p < 4; ++p) {
            int krow = ks * 16 + jk + r;
            int oct  = wn * 8 + 2 * p + jn;
            fa.b[ks * 4 + p] = smb + A_BYTES + krow * 256
                             + ((uint)(oct ^ (krow & 7)) << 4);
        }
    }
}

__device__ __forceinline__ void mma_chunk(const FragAddr& fa, int soff,
                                          float acc[2][8][4]) {
#pragma unroll
    for (int ks = 0; ks < 2; ++ks) {
        uint4 a[2];
#pragma unroll
        for (int mf = 0; mf < 2; ++mf)
            asm volatile("ld.shared.v4.b32 {%0,%1,%2,%3}, [%4];"
                : "=r"(a[mf].x), "=r"(a[mf].y), "=r"(a[mf].z), "=r"(a[mf].w)
                : "r"(fa.a[ks * 2 + mf] + soff));
        uint bf[8][2];
#pragma unroll
        for (int p = 0; p < 4; ++p) {
            uint d0, d1, d2, d3;
            asm volatile("ldmatrix.sync.aligned.m8n8.x4.trans.shared.b16 "
                "{%0,%1,%2,%3}, [%4];"
                : "=r"(d0), "=r"(d1), "=r"(d2), "=r"(d3)
                : "r"(fa.b[ks * 4 + p] + soff));
            bf[2 * p][0] = d0; bf[2 * p][1] = d1;
            bf[2 * p + 1][0] = d2; bf[2 * p + 1][1] = d3;
        }
#pragma unroll
        for (int mf = 0; mf < 2; ++mf)
#pragma unroll
            for (int nf = 0; nf < 8; ++nf)
                MMA16(acc[mf][nf], a[mf], bf[nf][0], bf[nf][1]);
    }
}

// ------------------------------------------------------ conv3x3 + BN + SiLU
__global__ __launch_bounds__(NTHR, 2) void k_conv3(
    const float* __restrict__ gamma, const float* __restrict__ beta,
    const float* __restrict__ mean,  const float* __restrict__ var)
{
    extern __shared__ __align__(16) char dsm[];
    __shared__ __align__(8) unsigned long long s_full[NSTG], s_empty[NSTG];
    const uint smb = smem_u32(dsm);
    const uint fullb = smem_u32(&s_full[0]);
    const uint emptyb = smem_u32(&s_empty[0]);

    const int tid = threadIdx.x;
    const int wrp = tid >> 5, lane = tid & 31;
    const int wm = wrp >> 1, wn = wrp & 1;
    const int h0  = blockIdx.x;
    const int ocg = blockIdx.y, oc0 = ocg * 128;
    const int b   = blockIdx.z;

    if (tid < NSTG) { MBAR_INIT(fullb + tid * 8, 1); MBAR_INIT(emptyb + tid * 8, 8); }
    __syncthreads();

    FragAddr fa;
    frag_init(fa, smb, wm, wn, lane);

    float acc[2][8][4];
#pragma unroll
    for (int i = 0; i < 2; ++i)
#pragma unroll
        for (int jj = 0; jj < 8; ++jj)
#pragma unroll
            for (int qq = 0; qq < 4; ++qq) acc[i][jj][qq] = 0.0f;

#define ISSUE_CONV(nit, s) do { \
        int kc_ = (nit) / 9, tap_ = (nit) - 9 * kc_; \
        int ky_ = tap_ / 3, kx_ = tap_ - 3 * ky_; \
        uint mbx = fullb + (s) * 8; \
        MBAR_EXPECT(mbx, 16384u); \
        BULK_G2S(smb + (s) * STAGE, \
                 (const char*)g_wA16 + (size_t)((nit) * 2 + ocg) * 8192, 8192u, mbx); \
        size_t blk_ = ((size_t)(kx_ * B_ + b) * 130 + (h0 + ky_)) * 4 + kc_; \
        BULK_G2S(smb + (s) * STAGE + A_BYTES, \
                 (const char*)g_xs + blk_ * 8192, 8192u, mbx); \
    } while (0)

    if (tid == 0) { ISSUE_CONV(0, 0); ISSUE_CONV(1, 1); ISSUE_CONV(2, 2); }

#pragma unroll 1
    for (int blk = 0; blk < 9; ++blk) {
        const uint ph = (uint)(blk & 1);
#pragma unroll
        for (int q = 0; q < 4; ++q) {
            const int it = blk * 4 + q;
            mbar_wait(fullb + q * 8, ph);
            mma_chunk(fa, q * STAGE, acc);
            if (lane == 0) MBAR_ARRIVE(emptyb + q * 8);
            if (tid == 0) {
                const int nx = it + 3;
                if (nx < 36) {
                    const int sn = (q + 3) & 3;
                    const int un = blk + (q >= 1 ? 1 : 0);
                    if (un >= 1) mbar_wait(emptyb + sn * 8, (uint)((un - 1) & 1));
                    ISSUE_CONV(nx, sn);
                }
            }
        }
    }
#undef ISSUE_CONV

    // epilogue: BN + SiLU -> g_yi (linear) + g_ys (shifted, swizzled tiles)
    const int kcg = (oc0 >> 5) + wm;          // global kc of this warp's 32 oc
    const int grp = (kcg >> 1) & 3;
    const int h = h0;
#pragma unroll
    for (int mf = 0; mf < 2; ++mf) {
        const int kk_a = mf * 16 + (lane >> 2), kk_b = kk_a + 8;
        const int oc_a = kcg * 32 + kk_a, oc_b = oc_a + 8;
        const float inva = __ldg(&gamma[oc_a]) * rsqrtf(__ldg(&var[oc_a]) + EPSBN);
        const float bba  = __ldg(&beta[oc_a]) - __ldg(&mean[oc_a]) * inva;
        const float invb = __ldg(&gamma[oc_b]) * rsqrtf(__ldg(&var[oc_b]) + EPSBN);
        const float bbb  = __ldg(&beta[oc_b]) - __ldg(&mean[oc_b]) * invb;
        const size_t ra = ((size_t)b * C2 + oc_a) * HW;
        const size_t rb = ((size_t)b * C2 + oc_b) * HW;
#pragma unroll
        for (int nf = 0; nf < 8; ++nf) {
            const int w = wn * 64 + nf * 8 + (lane & 3) * 2;
            const int off = h * W_ + w;
            float2 u, v;
            u.x = silu_f(acc[mf][nf][0] * inva + bba);
            u.y = silu_f(acc[mf][nf][1] * inva + bba);
            v.x = silu_f(acc[mf][nf][2] * invb + bbb);
            v.y = silu_f(acc[mf][nf][3] * invb + bbb);
            __half2 uh = __floats2half2_rn(u.x, u.y);
            __half2 vh = __floats2half2_rn(v.x, v.y);
            *(__half2*)(g_yi + ra + off) = uh;
            *(__half2*)(g_yi + rb + off) = vh;
            if (grp == 1) {                   // dest (h-1, w)
                if (h > 0) {
                    char* ysb = (char*)g_ys + ((size_t)(b * 128 + h - 1) * 8 + kcg) * 8192;
                    *(__half2*)(ysb + ysoff(kk_a, w)) = uh;
                    *(__half2*)(ysb + ysoff(kk_b, w)) = vh;
                }
            } else if (grp == 3) {            // dest (h+1, w)
                if (h < 127) {
                    char* ysb = (char*)g_ys + ((size_t)(b * 128 + h + 1) * 8 + kcg) * 8192;
                    *(__half2*)(ysb + ysoff(kk_a, w)) = uh;
                    *(__half2*)(ysb + ysoff(kk_b, w)) = vh;
                }
            } else if (grp == 0) {            // dest (h, w+1)
                char* ysb = (char*)g_ys + ((size_t)(b * 128 + h) * 8 + kcg) * 8192;
                *(__half*)(ysb + ysoff(kk_a, w + 1)) = __low2half(uh);
                *(__half*)(ysb + ysoff(kk_b, w + 1)) = __low2half(vh);
                if (w < 126) {
                    *(__half*)(ysb + ysoff(kk_a, w + 2)) = __high2half(uh);
                    *(__half*)(ysb + ysoff(kk_b, w + 2)) = __high2half(vh);
                }
            } else {                          // grp 2: dest (h, w-1)
                char* ysb = (char*)g_ys + ((size_t)(b * 128 + h) * 8 + kcg) * 8192;
                if (w > 0) {
                    *(__half*)(ysb + ysoff(kk_a, w - 1)) = __low2half(uh);
                    *(__half*)(ysb + ysoff(kk_b, w - 1)) = __low2half(vh);
                }
                *(__half*)(ysb + ysoff(kk_a, w)) = __high2half(uh);
                *(__half*)(ysb + ysoff(kk_b, w)) = __high2half(vh);
            }
        }
    }
}

// --------------------------- conv1x1(shifted y) + bias + BN + id + SiLU ----
__global__ __launch_bounds__(NTHR, 2) void k_pw(
    const float* __restrict__ b1,
    const float* __restrict__ gamma, const float* __restrict__ beta,
    const float* __restrict__ mean,  const float* __restrict__ var,
    float* __restrict__ out)
{
    extern __shared__ __align__(16) char dsm[];
    __shared__ __align__(8) unsigned long long s_full[NSTG], s_empty[NSTG];
    const uint smb = smem_u32(dsm);
    const uint fullb = smem_u32(&s_full[0]);
    const uint emptyb = smem_u32(&s_empty[0]);

    const int tid = threadIdx.x;
    const int wrp = tid >> 5, lane = tid & 31;
    const int wm = wrp >> 1, wn = wrp & 1;
    const int h0  = blockIdx.x;
    const int ocg = blockIdx.y, oc0 = ocg * 128;
    const int b   = blockIdx.z;

    if (tid < NSTG) { MBAR_INIT(fullb + tid * 8, 1); MBAR_INIT(emptyb + tid * 8, 8); }
    __syncthreads();

    FragAddr fa;
    frag_init(fa, smb, wm, wn, lane);

    float acc[2][8][4];
#pragma unroll
    for (int i = 0; i < 2; ++i)
#pragma unroll
        for (int jj = 0; jj < 8; ++jj)
#pragma unroll
            for (int qq = 0; qq < 4; ++qq) acc[i][jj][qq] = 0.0f;

#define ISSUE_PW(nit, s) do { \
        uint mbx = fullb + (s) * 8; \
        MBAR_EXPECT(mbx, 16384u); \
        BULK_G2S(smb + (s) * STAGE, \
                 (const char*)g_wB16 + (size_t)((nit) * 2 + ocg) * 8192, 8192u, mbx); \
        size_t blk_ = ((size_t)(b * 128 + h0) * 8 + (nit)); \
        BULK_G2S(smb + (s) * STAGE + A_BYTES, \
                 (const char*)g_ys + blk_ * 8192, 8192u, mbx); \
    } while (0)

    if (tid == 0) { ISSUE_PW(0, 0); ISSUE_PW(1, 1); ISSUE_PW(2, 2); }

#pragma unroll 1
    for (int blk = 0; blk < 2; ++blk) {
        const uint ph = (uint)(blk & 1);
#pragma unroll
        for (int q = 0; q < 4; ++q) {
            const int it = blk * 4 + q;
            mbar_wait(fullb + q * 8, ph);
            mma_chunk(fa, q * STAGE, acc);
            if (lane == 0) MBAR_ARRIVE(emptyb + q * 8);
            if (tid == 0) {
                const int nx = it + 3;
                if (nx < 8) {
                    const int sn = (q + 3) & 3;
                    const int un = blk + (q >= 1 ? 1 : 0);
                    if (un >= 1) mbar_wait(emptyb + sn * 8, (uint)((un - 1) & 1));
                    ISSUE_PW(nx, sn);
                }
            }
        }
    }
#undef ISSUE_PW

    // epilogue: +bias, BN, +identity(fp16), SiLU -> out (fp32)
    const int h = h0;
#pragma unroll
    for (int mf = 0; mf < 2; ++mf) {
        const int oc_a = oc0 + wm * 32 + mf * 16 + (lane >> 2);
        const int oc_b = oc_a + 8;
        const float inva = __ldg(&gamma[oc_a]) * rsqrtf(__ldg(&var[oc_a]) + EPSBN);
        const float bba  = __ldg(&beta[oc_a]) - __ldg(&mean[oc_a]) * inva;
        const float bsa  = __ldg(&b1[oc_a]);
        const float invb = __ldg(&gamma[oc_b]) * rsqrtf(__ldg(&var[oc_b]) + EPSBN);
        const float bbb  = __ldg(&beta[oc_b]) - __ldg(&mean[oc_b]) * invb;
        const float bsb  = __ldg(&b1[oc_b]);
        const size_t ra = ((size_t)b * C2 + oc_a) * HW;
        const size_t rb = ((size_t)b * C2 + oc_b) * HW;
#pragma unroll
        for (int nf = 0; nf < 8; ++nf) {
            const int w = wn * 64 + nf * 8 + (lane & 3) * 2;
            const int off = h * W_ + w;
            float2 ida = __half22float2(*(const __half2*)(g_yi + ra + off));
            float2 idb = __half22float2(*(const __half2*)(g_yi + rb + off));
            float2 u, v; float z;
            z = (acc[mf][nf][0] + bsa) * inva + bba + ida.x; u.x = silu_f(z);
            z = (acc[mf][nf][1] + bsa) * inva + bba + ida.y; u.y = silu_f(z);
            z = (acc[mf][nf][2] + bsb) * invb + bbb + idb.x; v.x = silu_f(z);
            z = (acc[mf][nf][3] + bsb) * invb + bbb + idb.y; v.y = silu_f(z);
            *(float2*)(out + ra + off) = u;
            *(float2*)(out + rb + off) = v;
        }
    }
}

// ---------------------------------------------------------------------------
extern "C" void kernel_launch(void* const* d_in, const int* in_sizes, int n_in,
                              void* d_out, int out_size)
{
    const float* x     = (const float*)d_in[0];
    const float* wconv = (const float*)d_in[1];
    const float* w1    = (const float*)d_in[2];
    const float* b1    = (const float*)d_in[3];
    const float* gamma = (const float*)d_in[4];
    const float* beta  = (const float*)d_in[5];
    const float* mean  = (const float*)d_in[6];
    const float* var   = (const float*)d_in[7];
    float* out = (float*)d_out;

    static bool attr_done = false;
    if (!attr_done) {
        cudaFuncSetAttribute(k_conv3, cudaFuncAttributeMaxDynamicSharedMemorySize, DSMEM_BYTES);
        cudaFuncSetAttribute(k_pw,    cudaFuncAttributeMaxDynamicSharedMemorySize, DSMEM_BYTES);
        attr_done = true;
    }

    k_repack<<<(C2 * C1 * 9 + C2 * C2 + 255) / 256, 256>>>(wconv, w1);
    k_prep_x<<<dim3(H_, B_), 256>>>(x);
    k_zero  <<<(Z_S0 + Z_S1 + Z_S2 + 255) / 256, 256>>>();

    dim3 grid(H_, 2, B_);   // 128 rows x 2 ocg x 16 batch = 4096 CTAs
    k_conv3<<<grid, NTHR, DSMEM_BYTES>>>(gamma, beta, mean, var);
    k_pw   <<<grid, NTHR, DSMEM_BYTES>>>(b1, gamma, beta, mean, var, out);
}